// round 1
// baseline (speedup 1.0000x reference)
#include <cuda_runtime.h>
#include <math.h>

#define NN 16384
#define DD 512
#define BSZ 16
#define MM 256
#define HH 8
#define DHH 64
#define LL 4
#define EE 262144
#define EPSV 1e-5f

// ---------------- scratch (static device globals; no runtime allocation) ----
__device__ float g_h [(size_t)NN*DD];
__device__ float g_b1[(size_t)NN*DD];
__device__ float g_b2[(size_t)NN*DD];
__device__ float g_b3[(size_t)NN*DD];
__device__ float g_kb[(size_t)BSZ*MM*DD];
__device__ float g_vb[(size_t)BSZ*MM*DD];
__device__ float g_u [(size_t)NN*4096];
__device__ float g_f [(size_t)NN*2048];
__device__ float g_deg [NN];
__device__ float g_dinv[NN];
__device__ int   g_edge[2*EE];
__device__ int   g_flag;
__device__ float g_sum  [DD];
__device__ float g_sumsq[DD];

// ---------------- edge-index dtype detect + convert ------------------------
__global__ void detect_kernel(const int* __restrict__ e32) {
    __shared__ int any;
    if (threadIdx.x == 0) any = 0;
    __syncthreads();
    int bad = 0;
    for (int i = threadIdx.x; i < 4096; i += 256)
        if (e32[2*i + 1] != 0) bad = 1;
    if (bad) any = 1;
    __syncthreads();
    if (threadIdx.x == 0) g_flag = (any == 0) ? 1 : 0;   // 1 => int64 payload
}

__global__ void convert_kernel(const void* __restrict__ e) {
    int i = blockIdx.x * 256 + threadIdx.x;
    if (i >= 2*EE) return;
    g_edge[i] = g_flag ? (int)((const long long*)e)[i] : ((const int*)e)[i];
}

// ---------------- misc small kernels ---------------------------------------
__global__ void zero_stats() {
    int i = blockIdx.x * 256 + threadIdx.x;
    if (i < NN) g_deg[i] = 0.f;
    if (i < DD) { g_sum[i] = 0.f; g_sumsq[i] = 0.f; }
}

__global__ void deg_kernel() {
    int e = blockIdx.x * 256 + threadIdx.x;
    if (e < EE) atomicAdd(&g_deg[g_edge[EE + e]], 1.f);
}

__global__ void dinv_kernel() {
    int i = blockIdx.x * 256 + threadIdx.x;
    if (i < NN) g_dinv[i] = rsqrtf(g_deg[i] + 1.f);   // +1 for self loop
}

// ---------------- BatchNorm (feature-wise over N) --------------------------
__global__ void bn_partial(const float* __restrict__ x) {
    int col = blockIdx.x * 256 + threadIdx.x;
    int r0  = blockIdx.y * 1024;
    float s = 0.f, ss = 0.f;
    for (int r = r0; r < r0 + 1024; r++) {
        float v = x[(size_t)r * DD + col];
        s += v; ss += v * v;
    }
    atomicAdd(&g_sum[col], s);
    atomicAdd(&g_sumsq[col], ss);
}

__global__ void bn_apply(const float* __restrict__ x, const float* __restrict__ w,
                         const float* __restrict__ b, float* __restrict__ y) {
    size_t i = (size_t)blockIdx.x * 256 + threadIdx.x;
    int c = (int)(i & (DD - 1));
    float mu  = g_sum[c] * (1.f / NN);
    float var = g_sumsq[c] * (1.f / NN) - mu * mu;
    y[i] = (x[i] - mu) * rsqrtf(var + EPSV) * w[c] + b[c];
}

// ---------------- LayerNorm (row-wise, one warp per row) --------------------
__global__ void ln_kernel(const float* __restrict__ x, const float* __restrict__ w,
                          const float* __restrict__ b, float* __restrict__ y) {
    int warp = (blockIdx.x * blockDim.x + threadIdx.x) >> 5;
    int lane = threadIdx.x & 31;
    if (warp >= NN) return;
    const float4* xr = (const float4*)(x + (size_t)warp * DD);
    float4 v[4];
    float s = 0.f, ss = 0.f;
#pragma unroll
    for (int i = 0; i < 4; i++) {
        v[i] = xr[lane + 32*i];
        s  += v[i].x + v[i].y + v[i].z + v[i].w;
        ss += v[i].x*v[i].x + v[i].y*v[i].y + v[i].z*v[i].z + v[i].w*v[i].w;
    }
#pragma unroll
    for (int o = 16; o; o >>= 1) {
        s  += __shfl_xor_sync(0xffffffffu, s,  o);
        ss += __shfl_xor_sync(0xffffffffu, ss, o);
    }
    float mean = s * (1.f / DD);
    float var  = ss * (1.f / DD) - mean * mean;
    float rs   = rsqrtf(var + EPSV);
    float4* yr = (float4*)(y + (size_t)warp * DD);
    const float4* wr = (const float4*)w;
    const float4* br = (const float4*)b;
#pragma unroll
    for (int i = 0; i < 4; i++) {
        float4 wv = wr[lane + 32*i], bv = br[lane + 32*i], o4;
        o4.x = (v[i].x - mean) * rs * wv.x + bv.x;
        o4.y = (v[i].y - mean) * rs * wv.y + bv.y;
        o4.z = (v[i].z - mean) * rs * wv.z + bv.z;
        o4.w = (v[i].w - mean) * rs * wv.w + bv.w;
        yr[lane + 32*i] = o4;
    }
}

// ---------------- SGEMM: C = A[MxK] * B[KxN] (+bias[N]) (+add[MxN]) ---------
__global__ __launch_bounds__(256) void sgemm(
    const float* __restrict__ A, const float* __restrict__ B,
    float* __restrict__ C, int M, int N, int K,
    const float* __restrict__ bias, const float* __restrict__ add)
{
    __shared__ float As[8][128];
    __shared__ float Bs[8][128];
    const int tid  = threadIdx.x;
    const int bm   = blockIdx.y * 128;
    const int bn   = blockIdx.x * 128;
    const int arow = tid >> 1, acol = (tid & 1) << 2;
    const int brow = tid >> 5, bcol = (tid & 31) << 2;
    const float* Ap = A + (size_t)(bm + arow) * K + acol;
    const float* Bp = B + (size_t)brow * N + bn + bcol;
    const int tx = tid & 15, ty = tid >> 4;

    float acc[8][8];
#pragma unroll
    for (int i = 0; i < 8; i++)
#pragma unroll
        for (int j = 0; j < 8; j++) acc[i][j] = 0.f;

    float4 a = *(const float4*)Ap;
    float4 b = *(const float4*)Bp;
    for (int k0 = 0; k0 < K; k0 += 8) {
        As[acol+0][arow] = a.x; As[acol+1][arow] = a.y;
        As[acol+2][arow] = a.z; As[acol+3][arow] = a.w;
        *(float4*)&Bs[brow][bcol] = b;
        __syncthreads();
        if (k0 + 8 < K) {
            a = *(const float4*)(Ap + k0 + 8);
            b = *(const float4*)(Bp + (size_t)(k0 + 8) * N);
        }
#pragma unroll
        for (int kk = 0; kk < 8; kk++) {
            float af[8], bf[8];
            *(float4*)&af[0] = *(const float4*)&As[kk][ty * 4];
            *(float4*)&af[4] = *(const float4*)&As[kk][64 + ty * 4];
            *(float4*)&bf[0] = *(const float4*)&Bs[kk][tx * 4];
            *(float4*)&bf[4] = *(const float4*)&Bs[kk][64 + tx * 4];
#pragma unroll
            for (int i = 0; i < 8; i++)
#pragma unroll
                for (int j = 0; j < 8; j++)
                    acc[i][j] = fmaf(af[i], bf[j], acc[i][j]);
        }
        __syncthreads();
    }

#pragma unroll
    for (int ih = 0; ih < 2; ih++)
#pragma unroll
    for (int i = 0; i < 4; i++) {
        int row = bm + ih * 64 + ty * 4 + i;
#pragma unroll
        for (int jh = 0; jh < 2; jh++) {
            int col = bn + jh * 64 + tx * 4;
            float4 r;
            r.x = acc[ih*4+i][jh*4+0]; r.y = acc[ih*4+i][jh*4+1];
            r.z = acc[ih*4+i][jh*4+2]; r.w = acc[ih*4+i][jh*4+3];
            if (bias) {
                float4 bb = *(const float4*)(bias + col);
                r.x += bb.x; r.y += bb.y; r.z += bb.z; r.w += bb.w;
            }
            if (add) {
                float4 aa = *(const float4*)(add + (size_t)row * N + col);
                r.x += aa.x; r.y += aa.y; r.z += aa.z; r.w += aa.w;
            }
            *(float4*)(C + (size_t)row * N + col) = r;
        }
    }
}

// ---------------- GCN scatter ------------------------------------------------
// out[i,:] = hw[i,:]*dinv[i]^2 + bias  (+extra[i,:])   (self-loop + bias + residual)
__global__ void gcn_init(const float* __restrict__ hw, const float* __restrict__ bias,
                         const float* __restrict__ extra, float* __restrict__ out) {
    size_t i = (size_t)blockIdx.x * 256 + threadIdx.x;
    int r = (int)(i >> 9), c = (int)(i & 511);
    float dv = g_dinv[r];
    float v = hw[i] * dv * dv + bias[c];
    if (extra) v += extra[i];
    out[i] = v;
}

__global__ void gcn_scatter(const float* __restrict__ hw, float* __restrict__ out) {
    int wid  = (blockIdx.x * blockDim.x + threadIdx.x) >> 5;
    int lane = threadIdx.x & 31;
    if (wid >= EE) return;
    int s = g_edge[wid], d = g_edge[EE + wid];
    float w = g_dinv[s] * g_dinv[d];
    const float* hp = hw + (size_t)s * DD;
    float* op = out + (size_t)d * DD;
#pragma unroll
    for (int i = 0; i < 16; i++) {
        int c = lane + 32 * i;
        atomicAdd(op + c, hp[c] * w);
    }
}

// ---------------- fused cross-attention -------------------------------------
// grid (H, BS), 256 threads; K/V for one (b,h) resident in smem (128 KB)
__global__ __launch_bounds__(256) void attn_kernel(
    const float* __restrict__ Q, const float* __restrict__ Kc,
    const float* __restrict__ Vc, float* __restrict__ O)
{
    extern __shared__ float smem[];
    float* Ks = smem;             // [256][64]
    float* Vs = smem + 256 * 64;  // [256][64]
    const int h = blockIdx.x, b = blockIdx.y;
    const int tid = threadIdx.x;
    for (int i = tid; i < 256 * 16; i += 256) {
        int m = i >> 4, d4 = (i & 15) << 2;
        size_t g = (size_t)(b * MM + m) * DD + h * DHH + d4;
        *(float4*)&Ks[m * 64 + d4] = *(const float4*)(Kc + g);
        *(float4*)&Vs[m * 64 + d4] = *(const float4*)(Vc + g);
    }
    __syncthreads();
    const float scale = 0.125f;   // 64^-0.5
    for (int r = 0; r < 4; r++) {
        int n = r * 256 + tid;
        const float* qp = Q + (size_t)(b * 1024 + n) * DD + h * DHH;
        float q[64];
#pragma unroll
        for (int i = 0; i < 16; i++) *(float4*)&q[i*4] = *(const float4*)(qp + i*4);
        // pass 1: max + sum-exp (online)
        float mx = -1e30f, s = 0.f;
        for (int m = 0; m < 256; m++) {
            float dot = 0.f;
#pragma unroll
            for (int d = 0; d < 64; d++) dot = fmaf(q[d], Ks[m*64 + d], dot);
            dot *= scale;
            if (dot > mx) { s = s * __expf(mx - dot) + 1.f; mx = dot; }
            else            s += __expf(dot - mx);
        }
        float inv = 1.f / s;
        // pass 2: recompute scores, accumulate V
        float o[64];
#pragma unroll
        for (int d = 0; d < 64; d++) o[d] = 0.f;
        for (int m = 0; m < 256; m++) {
            float dot = 0.f;
#pragma unroll
            for (int d = 0; d < 64; d++) dot = fmaf(q[d], Ks[m*64 + d], dot);
            float w = __expf(dot * scale - mx);
#pragma unroll
            for (int d = 0; d < 64; d++) o[d] = fmaf(w, Vs[m*64 + d], o[d]);
        }
        float* op = O + (size_t)(b * 1024 + n) * DD + h * DHH;
#pragma unroll
        for (int i = 0; i < 16; i++) {
            float4 v;
            v.x = o[i*4+0] * inv; v.y = o[i*4+1] * inv;
            v.z = o[i*4+2] * inv; v.w = o[i*4+3] * inv;
            *(float4*)(op + i*4) = v;
        }
    }
}

// ---------------- GEGLU elementwise -----------------------------------------
__global__ void geglu_kernel() {
    size_t i = (size_t)blockIdx.x * 256 + threadIdx.x;  // over NN*2048/4 float4s
    int r = (int)(i >> 9), c4 = (int)(i & 511);
    const float4* up = (const float4*)g_u;
    float4 val  = up[(size_t)r * 1024 + c4];
    float4 gate = up[(size_t)r * 1024 + 512 + c4];
    float4 o;
    o.x = val.x * 0.5f * gate.x * (1.f + erff(gate.x * 0.70710678f));
    o.y = val.y * 0.5f * gate.y * (1.f + erff(gate.y * 0.70710678f));
    o.z = val.z * 0.5f * gate.z * (1.f + erff(gate.z * 0.70710678f));
    o.w = val.w * 0.5f * gate.w * (1.f + erff(gate.w * 0.70710678f));
    ((float4*)g_f)[i] = o;
}

// ---------------- host orchestration ----------------------------------------
extern "C" void kernel_launch(void* const* d_in, const int* in_sizes, int n_in,
                              void* d_out, int out_size)
{
    const float* x        = (const float*)d_in[0];
    const void*  edges    = d_in[1];
    const float* cond     = (const float*)d_in[2];
    const float* bn_w     = (const float*)d_in[3];
    const float* bn_b     = (const float*)d_in[4];
    const float* gcn_in_w = (const float*)d_in[5];
    const float* gcn_in_b = (const float*)d_in[6];
    const float* gcn_out_w= (const float*)d_in[7];
    const float* gcn_out_b= (const float*)d_in[8];
    const float* Wq       = (const float*)d_in[9];
    const float* Wk       = (const float*)d_in[10];
    const float* Wv       = (const float*)d_in[11];
    const float* Wo       = (const float*)d_in[12];
    const float* ln2_w    = (const float*)d_in[13];
    const float* ln2_b    = (const float*)d_in[14];
    const float* ln3_w    = (const float*)d_in[15];
    const float* ln3_b    = (const float*)d_in[16];
    const float* geglu_w  = (const float*)d_in[17];
    const float* geglu_b  = (const float*)d_in[18];
    const float* ffo_w    = (const float*)d_in[19];
    const float* ffo_b    = (const float*)d_in[20];
    float* out = (float*)d_out;

    float *h, *b1, *b2, *b3, *kb, *vb, *f;
    cudaGetSymbolAddress((void**)&h,  g_h);
    cudaGetSymbolAddress((void**)&b1, g_b1);
    cudaGetSymbolAddress((void**)&b2, g_b2);
    cudaGetSymbolAddress((void**)&b3, g_b3);
    cudaGetSymbolAddress((void**)&kb, g_kb);
    cudaGetSymbolAddress((void**)&vb, g_vb);
    cudaGetSymbolAddress((void**)&f,  g_f);
    float* u;
    cudaGetSymbolAddress((void**)&u,  g_u);

    cudaFuncSetAttribute(attn_kernel,
                         cudaFuncAttributeMaxDynamicSharedMemorySize, 131072);

    // ---- edge index normalize + degrees ----
    detect_kernel<<<1, 256>>>((const int*)edges);
    convert_kernel<<<(2*EE + 255) / 256, 256>>>(edges);
    zero_stats<<<NN / 256, 256>>>();
    deg_kernel<<<EE / 256, 256>>>();
    dinv_kernel<<<NN / 256, 256>>>();

    // ---- BatchNorm ----
    bn_partial<<<dim3(2, 16), 256>>>(x);
    bn_apply<<<(NN * DD) / 256, 256>>>(x, bn_w, bn_b, b1);

    // ---- GCN in: h = scatter(bn(x) @ W) + b ----
    sgemm<<<dim3(DD/128, NN/128), 256>>>(b1, gcn_in_w, b2, NN, DD, DD, nullptr, nullptr);
    gcn_init<<<(NN * DD) / 256, 256>>>(b2, gcn_in_b, nullptr, h);
    gcn_scatter<<<EE / 8, 256>>>(b2, h);

    // ---- transformer layers ----
    for (int i = 0; i < LL; i++) {
        ln_kernel<<<NN / 8, 256>>>(h, ln2_w + i*DD, ln2_b + i*DD, b1);
        sgemm<<<dim3(4, 128), 256>>>(b1, Wq + (size_t)i*DD*512, b2, NN, 512, DD, nullptr, nullptr);
        sgemm<<<dim3(4, 32), 256>>>(cond, Wk + (size_t)i*DD*512, kb, BSZ*MM, 512, DD, nullptr, nullptr);
        sgemm<<<dim3(4, 32), 256>>>(cond, Wv + (size_t)i*DD*512, vb, BSZ*MM, 512, DD, nullptr, nullptr);
        attn_kernel<<<dim3(HH, BSZ), 256, 131072>>>(b2, kb, vb, b3);
        sgemm<<<dim3(4, 128), 256>>>(b3, Wo + (size_t)i*512*DD, h, NN, DD, 512, nullptr, h);
        ln_kernel<<<NN / 8, 256>>>(h, ln3_w + i*DD, ln3_b + i*DD, b1);
        sgemm<<<dim3(32, 128), 256>>>(b1, geglu_w + (size_t)i*DD*4096, u, NN, 4096, DD,
                                      geglu_b + (size_t)i*4096, nullptr);
        geglu_kernel<<<(NN * 2048 / 4) / 256, 256>>>();
        sgemm<<<dim3(4, 128), 256>>>(f, ffo_w + (size_t)i*2048*DD, h, NN, DD, 2048,
                                     ffo_b + i*DD, h);
    }

    // ---- GCN out + residual (folded into init) ----
    sgemm<<<dim3(4, 128), 256>>>(h, gcn_out_w, b1, NN, DD, DD, nullptr, nullptr);
    gcn_init<<<(NN * DD) / 256, 256>>>(b1, gcn_out_b, x, out);
    gcn_scatter<<<EE / 8, 256>>>(b1, out);
}

// round 5
// speedup vs baseline: 1.5267x; 1.5267x over previous
#include <cuda_runtime.h>
#include <cuda_bf16.h>
#include <math.h>
#include <stdint.h>

#define NN 16384
#define DD 512
#define BSZ 16
#define MM 256
#define HH 8
#define DHH 64
#define LL 4
#define EE 262144
#define EPSV 1e-5f

// ---------------- scratch (static device globals; no runtime allocation) ----
__device__ float g_h [(size_t)NN*DD];
__device__ float g_b1[(size_t)NN*DD];
__device__ float g_b2[(size_t)NN*DD];
__device__ float g_b3[(size_t)NN*DD];
__device__ float g_kb[(size_t)BSZ*MM*DD];
__device__ float g_vb[(size_t)BSZ*MM*DD];
__device__ float g_u [(size_t)NN*4096];
__device__ float g_f [(size_t)NN*2048];
__device__ float g_deg [NN];
__device__ float g_dinv[NN];
__device__ int   g_edge[2*EE];
__device__ int   g_flag;
__device__ float g_sum  [DD];
__device__ float g_sumsq[DD];
// split-bf16 transposed weights: [N][K] K-major, hi and lo terms
#define WT_TOTAL 17301504ULL
__device__ __nv_bfloat16 g_bt0[WT_TOTAL];
__device__ __nv_bfloat16 g_bt1[WT_TOTAL];

// ======================= helpers =============================================
__device__ __forceinline__ uint32_t smem_u32(const void* p) {
    uint32_t a;
    asm("{ .reg .u64 t; cvta.to.shared.u64 t, %1; cvt.u32.u64 %0, t; }"
        : "=r"(a) : "l"(p));
    return a;
}
#define SW128(b) ((b) ^ (((b) >> 3) & 0x70))

#define LDSM_X4(r, addr) \
    asm volatile("ldmatrix.sync.aligned.m8n8.x4.shared.b16 {%0,%1,%2,%3}, [%4];" \
        : "=r"((r)[0]), "=r"((r)[1]), "=r"((r)[2]), "=r"((r)[3]) : "r"(addr))

__device__ __forceinline__ void mma16816(float* c, const uint32_t* a, const uint32_t* b) {
    asm volatile("mma.sync.aligned.m16n8k16.row.col.f32.bf16.bf16.f32 "
        "{%0,%1,%2,%3}, {%4,%5,%6,%7}, {%8,%9}, {%0,%1,%2,%3};"
        : "+f"(c[0]), "+f"(c[1]), "+f"(c[2]), "+f"(c[3])
        : "r"(a[0]), "r"(a[1]), "r"(a[2]), "r"(a[3]), "r"(b[0]), "r"(b[1]));
}

#define CP_ASYNC16(dst, src) \
    asm volatile("cp.async.cg.shared.global [%0], [%1], 16;" :: "r"(dst), "l"(src))
#define CP_COMMIT()  asm volatile("cp.async.commit_group;" ::: "memory")
#define CP_WAIT0()   asm volatile("cp.async.wait_group 0;" ::: "memory")

// ---------------- weight transpose + bf16 split -----------------------------
// W[K][N] fp32 -> O0,O1 [N][K] bf16 (hi, lo residual)
__global__ void wsplit(const float* __restrict__ W, __nv_bfloat16* __restrict__ O0,
                       __nv_bfloat16* __restrict__ O1, int K, int N) {
    __shared__ float t[32][33];
    int bn = blockIdx.x * 32, bk = blockIdx.y * 32;
    int tx = threadIdx.x, ty = threadIdx.y;
    for (int i = ty; i < 32; i += 8)
        t[i][tx] = W[(size_t)(bk + i) * N + bn + tx];
    __syncthreads();
    for (int i = ty; i < 32; i += 8) {
        float v = t[tx][i];
        __nv_bfloat16 h0 = __float2bfloat16(v);
        float r = v - __bfloat162float(h0);
        size_t o = (size_t)(bn + i) * K + bk + tx;
        O0[o] = h0;
        O1[o] = __float2bfloat16(r);
    }
}

// ---------------- HMMA split-bf16 GEMM ---------------------------------------
// C[M,N] = A[M,K] (fp32) * W[K,N]; W pre-split as B0,B1 [N][K] bf16 (K-major).
// CTA 128x128, 8 warps (2m x 4n), warp tile 64x32, K-chunk 64, 2 stages.
// Stage layout (64KB): A0 @0, A1 @16K, B0 @32K, B1 @48K. Total 128KB.
#define MM_SMEM 131072
#define STG 65536

__device__ __forceinline__ void mm_issueB(const __nv_bfloat16* __restrict__ B0,
                                          const __nv_bfloat16* __restrict__ B1,
                                          uint32_t sb, int stage, int bn, int K,
                                          int kc, int tid) {
    uint32_t base0 = sb + stage * STG + 32768;
    uint32_t base1 = base0 + 16384;
#pragma unroll
    for (int i = 0; i < 4; i++) {
        int idx = i * 256 + tid;
        int row = idx >> 3, chunk = idx & 7;
        size_t src = (size_t)(bn + row) * K + (kc << 6) + (chunk << 3);
        uint32_t d = SW128((uint32_t)(row * 128 + chunk * 16));
        CP_ASYNC16(base0 + d, B0 + src);
        CP_ASYNC16(base1 + d, B1 + src);
    }
}

__global__ __launch_bounds__(256, 1)
void mm_gemm(const float* __restrict__ A, const __nv_bfloat16* __restrict__ B0,
             const __nv_bfloat16* __restrict__ B1, float* __restrict__ C,
             int M, int N, int K, const float* __restrict__ bias,
             const float* __restrict__ add)
{
    extern __shared__ char smem[];
    uint32_t sb = smem_u32(smem);
    const int tid = threadIdx.x, wid = tid >> 5, lane = tid & 31;
    const int bm = blockIdx.y * 128, bn = blockIdx.x * 128;
    const int wm = wid >> 2, wn = wid & 3;
    const int nch = K >> 6;

    float acc[4][4][4];
#pragma unroll
    for (int i = 0; i < 4; i++)
#pragma unroll
        for (int j = 0; j < 4; j++)
#pragma unroll
            for (int k = 0; k < 4; k++) acc[i][j][k] = 0.f;

    // prologue: B chunk0 -> stage0; A chunk0 -> regs
    mm_issueB(B0, B1, sb, 0, bn, K, 0, tid);
    CP_COMMIT();
    const int arow = tid >> 1, ahalf = (tid & 1) << 5;
    const float* aptr = A + (size_t)(bm + arow) * K + ahalf;
    float4 ar[8];
#pragma unroll
    for (int i = 0; i < 8; i++) ar[i] = ((const float4*)aptr)[i];

    for (int kc = 0; kc < nch; kc++) {
        const int s = kc & 1;
        const uint32_t stA0 = sb + s * STG;
        const uint32_t stA1 = stA0 + 16384;
        const uint32_t stB0 = stA0 + 32768;
        const uint32_t stB1 = stA0 + 49152;

        CP_WAIT0();
        // store A regs (split hi/lo) into stage s
        {
#pragma unroll
            for (int i = 0; i < 8; i++) {
                float4 v = ar[i];
                __nv_bfloat16 hx = __float2bfloat16(v.x), hy = __float2bfloat16(v.y);
                __nv_bfloat16 hz = __float2bfloat16(v.z), hw = __float2bfloat16(v.w);
                __nv_bfloat162 H0 = __halves2bfloat162(hx, hy);
                __nv_bfloat162 H1 = __halves2bfloat162(hz, hw);
                __nv_bfloat162 L0 = __halves2bfloat162(
                    __float2bfloat16(v.x - __bfloat162float(hx)),
                    __float2bfloat16(v.y - __bfloat162float(hy)));
                __nv_bfloat162 L1 = __halves2bfloat162(
                    __float2bfloat16(v.z - __bfloat162float(hz)),
                    __float2bfloat16(v.w - __bfloat162float(hw)));
                uint32_t b = (uint32_t)(arow * 128 + ((ahalf + i * 4) << 1));
                uint32_t sw = SW128(b);
                *(uint2*)(smem + (s * STG) + sw) =
                    make_uint2(*(uint32_t*)&H0, *(uint32_t*)&H1);
                *(uint2*)(smem + (s * STG + 16384) + sw) =
                    make_uint2(*(uint32_t*)&L0, *(uint32_t*)&L1);
            }
        }
        __syncthreads();

        if (kc + 1 < nch) {
            mm_issueB(B0, B1, sb, s ^ 1, bn, K, kc + 1, tid);
            CP_COMMIT();
#pragma unroll
            for (int i = 0; i < 8; i++)
                ar[i] = ((const float4*)(aptr + ((kc + 1) << 6)))[i];
        }

        // compute on stage s: 4 k16 steps
#pragma unroll
        for (int k16 = 0; k16 < 4; k16++) {
            const int kch = k16 << 1;   // 16B-chunk index base (k0/8)
            uint32_t a0[4][4], a1[4][4];
#pragma unroll
            for (int mf = 0; mf < 4; mf++) {
                int row = wm * 64 + mf * 16 + (lane & 15);
                int chunk = kch + (lane >> 4);
                uint32_t off = SW128((uint32_t)(row * 128 + chunk * 16));
                LDSM_X4(a0[mf], stA0 + off);
                LDSM_X4(a1[mf], stA1 + off);
            }
            uint32_t b0[4][2], b1[4][2];
#pragma unroll
            for (int np = 0; np < 2; np++) {
                int nrow = wn * 32 + np * 16 + ((lane >> 4) << 3) + (lane & 7);
                int chunk = kch + ((lane >> 3) & 1);
                uint32_t off = SW128((uint32_t)(nrow * 128 + chunk * 16));
                uint32_t r[4];
                LDSM_X4(r, stB0 + off);
                b0[2*np][0] = r[0]; b0[2*np][1] = r[1];
                b0[2*np+1][0] = r[2]; b0[2*np+1][1] = r[3];
                LDSM_X4(r, stB1 + off);
                b1[2*np][0] = r[0]; b1[2*np][1] = r[1];
                b1[2*np+1][0] = r[2]; b1[2*np+1][1] = r[3];
            }
#pragma unroll
            for (int mf = 0; mf < 4; mf++)
#pragma unroll
                for (int nf = 0; nf < 4; nf++) {
                    mma16816(acc[mf][nf], a0[mf], b0[nf]);
                    mma16816(acc[mf][nf], a0[mf], b1[nf]);
                    mma16816(acc[mf][nf], a1[mf], b0[nf]);
                }
        }
        __syncthreads();
    }

    // epilogue: write acc to C with optional bias/add
#pragma unroll
    for (int mf = 0; mf < 4; mf++) {
#pragma unroll
        for (int nf = 0; nf < 4; nf++) {
            int r0 = bm + wm * 64 + mf * 16 + (lane >> 2);
            int c0 = bn + wn * 32 + nf * 8 + ((lane & 3) << 1);
            float2 v0 = make_float2(acc[mf][nf][0], acc[mf][nf][1]);
            float2 v1 = make_float2(acc[mf][nf][2], acc[mf][nf][3]);
            if (bias) {
                float2 bb = *(const float2*)(bias + c0);
                v0.x += bb.x; v0.y += bb.y; v1.x += bb.x; v1.y += bb.y;
            }
            if (add) {
                float2 a0v = *(const float2*)(add + (size_t)r0 * N + c0);
                float2 a1v = *(const float2*)(add + (size_t)(r0 + 8) * N + c0);
                v0.x += a0v.x; v0.y += a0v.y; v1.x += a1v.x; v1.y += a1v.y;
            }
            *(float2*)(C + (size_t)r0 * N + c0) = v0;
            *(float2*)(C + (size_t)(r0 + 8) * N + c0) = v1;
        }
    }
}

// ---------------- edge-index dtype detect + convert ------------------------
__global__ void detect_kernel(const int* __restrict__ e32) {
    __shared__ int any;
    if (threadIdx.x == 0) any = 0;
    __syncthreads();
    int bad = 0;
    for (int i = threadIdx.x; i < 4096; i += 256)
        if (e32[2*i + 1] != 0) bad = 1;
    if (bad) any = 1;
    __syncthreads();
    if (threadIdx.x == 0) g_flag = (any == 0) ? 1 : 0;   // 1 => int64 payload
}

__global__ void convert_kernel(const void* __restrict__ e) {
    int i = blockIdx.x * 256 + threadIdx.x;
    if (i >= 2*EE) return;
    g_edge[i] = g_flag ? (int)((const long long*)e)[i] : ((const int*)e)[i];
}

// ---------------- misc small kernels ---------------------------------------
__global__ void zero_stats() {
    int i = blockIdx.x * 256 + threadIdx.x;
    if (i < NN) g_deg[i] = 0.f;
    if (i < DD) { g_sum[i] = 0.f; g_sumsq[i] = 0.f; }
}

__global__ void deg_kernel() {
    int e = blockIdx.x * 256 + threadIdx.x;
    if (e < EE) atomicAdd(&g_deg[g_edge[EE + e]], 1.f);
}

__global__ void dinv_kernel() {
    int i = blockIdx.x * 256 + threadIdx.x;
    if (i < NN) g_dinv[i] = rsqrtf(g_deg[i] + 1.f);
}

// ---------------- BatchNorm --------------------------------------------------
__global__ void bn_partial(const float* __restrict__ x) {
    int col = blockIdx.x * 256 + threadIdx.x;
    int r0  = blockIdx.y * 1024;
    float s = 0.f, ss = 0.f;
    for (int r = r0; r < r0 + 1024; r++) {
        float v = x[(size_t)r * DD + col];
        s += v; ss += v * v;
    }
    atomicAdd(&g_sum[col], s);
    atomicAdd(&g_sumsq[col], ss);
}

__global__ void bn_apply(const float* __restrict__ x, const float* __restrict__ w,
                         const float* __restrict__ b, float* __restrict__ y) {
    size_t i = (size_t)blockIdx.x * 256 + threadIdx.x;
    int c = (int)(i & (DD - 1));
    float mu  = g_sum[c] * (1.f / NN);
    float var = g_sumsq[c] * (1.f / NN) - mu * mu;
    y[i] = (x[i] - mu) * rsqrtf(var + EPSV) * w[c] + b[c];
}

// ---------------- LayerNorm --------------------------------------------------
__global__ void ln_kernel(const float* __restrict__ x, const float* __restrict__ w,
                          const float* __restrict__ b, float* __restrict__ y) {
    int warp = (blockIdx.x * blockDim.x + threadIdx.x) >> 5;
    int lane = threadIdx.x & 31;
    if (warp >= NN) return;
    const float4* xr = (const float4*)(x + (size_t)warp * DD);
    float4 v[4];
    float s = 0.f, ss = 0.f;
#pragma unroll
    for (int i = 0; i < 4; i++) {
        v[i] = xr[lane + 32*i];
        s  += v[i].x + v[i].y + v[i].z + v[i].w;
        ss += v[i].x*v[i].x + v[i].y*v[i].y + v[i].z*v[i].z + v[i].w*v[i].w;
    }
#pragma unroll
    for (int o = 16; o; o >>= 1) {
        s  += __shfl_xor_sync(0xffffffffu, s,  o);
        ss += __shfl_xor_sync(0xffffffffu, ss, o);
    }
    float mean = s * (1.f / DD);
    float var  = ss * (1.f / DD) - mean * mean;
    float rs   = rsqrtf(var + EPSV);
    float4* yr = (float4*)(y + (size_t)warp * DD);
    const float4* wr = (const float4*)w;
    const float4* br = (const float4*)b;
#pragma unroll
    for (int i = 0; i < 4; i++) {
        float4 wv = wr[lane + 32*i], bv = br[lane + 32*i], o4;
        o4.x = (v[i].x - mean) * rs * wv.x + bv.x;
        o4.y = (v[i].y - mean) * rs * wv.y + bv.y;
        o4.z = (v[i].z - mean) * rs * wv.z + bv.z;
        o4.w = (v[i].w - mean) * rs * wv.w + bv.w;
        yr[lane + 32*i] = o4;
    }
}

// ---------------- GCN scatter ------------------------------------------------
__global__ void gcn_init(const float* __restrict__ hw, const float* __restrict__ bias,
                         const float* __restrict__ extra, float* __restrict__ out) {
    size_t i = (size_t)blockIdx.x * 256 + threadIdx.x;
    int r = (int)(i >> 9), c = (int)(i & 511);
    float dv = g_dinv[r];
    float v = hw[i] * dv * dv + bias[c];
    if (extra) v += extra[i];
    out[i] = v;
}

__global__ void gcn_scatter(const float* __restrict__ hw, float* __restrict__ out) {
    int wid  = (blockIdx.x * blockDim.x + threadIdx.x) >> 5;
    int lane = threadIdx.x & 31;
    if (wid >= EE) return;
    int s = g_edge[wid], d = g_edge[EE + wid];
    float w = g_dinv[s] * g_dinv[d];
    const float* hp = hw + (size_t)s * DD;
    float* op = out + (size_t)d * DD;
#pragma unroll
    for (int i = 0; i < 16; i++) {
        int c = lane + 32 * i;
        atomicAdd(op + c, hp[c] * w);
    }
}

// ---------------- fused cross-attention -------------------------------------
__global__ __launch_bounds__(256) void attn_kernel(
    const float* __restrict__ Q, const float* __restrict__ Kc,
    const float* __restrict__ Vc, float* __restrict__ O)
{
    extern __shared__ float smemf[];
    float* Ks = smemf;
    float* Vs = smemf + 256 * 64;
    const int h = blockIdx.x, b = blockIdx.y;
    const int tid = threadIdx.x;
    for (int i = tid; i < 256 * 16; i += 256) {
        int m = i >> 4, d4 = (i & 15) << 2;
        size_t g = (size_t)(b * MM + m) * DD + h * DHH + d4;
        *(float4*)&Ks[m * 64 + d4] = *(const float4*)(Kc + g);
        *(float4*)&Vs[m * 64 + d4] = *(const float4*)(Vc + g);
    }
    __syncthreads();
    const float scale = 0.125f;
    for (int r = 0; r < 4; r++) {
        int n = r * 256 + tid;
        const float* qp = Q + (size_t)(b * 1024 + n) * DD + h * DHH;
        float q[64];
#pragma unroll
        for (int i = 0; i < 16; i++) *(float4*)&q[i*4] = *(const float4*)(qp + i*4);
        float mx = -1e30f, s = 0.f;
        for (int m = 0; m < 256; m++) {
            float dot = 0.f;
#pragma unroll
            for (int d = 0; d < 64; d++) dot = fmaf(q[d], Ks[m*64 + d], dot);
            dot *= scale;
            if (dot > mx) { s = s * __expf(mx - dot) + 1.f; mx = dot; }
            else            s += __expf(dot - mx);
        }
        float inv = 1.f / s;
        float o[64];
#pragma unroll
        for (int d = 0; d < 64; d++) o[d] = 0.f;
        for (int m = 0; m < 256; m++) {
            float dot = 0.f;
#pragma unroll
            for (int d = 0; d < 64; d++) dot = fmaf(q[d], Ks[m*64 + d], dot);
            float w = __expf(dot * scale - mx);
#pragma unroll
            for (int d = 0; d < 64; d++) o[d] = fmaf(w, Vs[m*64 + d], o[d]);
        }
        float* op = O + (size_t)(b * 1024 + n) * DD + h * DHH;
#pragma unroll
        for (int i = 0; i < 16; i++) {
            float4 v;
            v.x = o[i*4+0] * inv; v.y = o[i*4+1] * inv;
            v.z = o[i*4+2] * inv; v.w = o[i*4+3] * inv;
            *(float4*)(op + i*4) = v;
        }
    }
}

// ---------------- GEGLU elementwise -----------------------------------------
__global__ void geglu_kernel() {
    size_t i = (size_t)blockIdx.x * 256 + threadIdx.x;
    int r = (int)(i >> 9), c4 = (int)(i & 511);
    const float4* up = (const float4*)g_u;
    float4 val  = up[(size_t)r * 1024 + c4];
    float4 gate = up[(size_t)r * 1024 + 512 + c4];
    float4 o;
    o.x = val.x * 0.5f * gate.x * (1.f + erff(gate.x * 0.70710678f));
    o.y = val.y * 0.5f * gate.y * (1.f + erff(gate.y * 0.70710678f));
    o.z = val.z * 0.5f * gate.z * (1.f + erff(gate.z * 0.70710678f));
    o.w = val.w * 0.5f * gate.w * (1.f + erff(gate.w * 0.70710678f));
    ((float4*)g_f)[i] = o;
}

// ---------------- host orchestration ----------------------------------------
extern "C" void kernel_launch(void* const* d_in, const int* in_sizes, int n_in,
                              void* d_out, int out_size)
{
    const float* x        = (const float*)d_in[0];
    const void*  edges    = d_in[1];
    const float* cond     = (const float*)d_in[2];
    const float* bn_w     = (const float*)d_in[3];
    const float* bn_b     = (const float*)d_in[4];
    const float* gcn_in_w = (const float*)d_in[5];
    const float* gcn_in_b = (const float*)d_in[6];
    const float* gcn_out_w= (const float*)d_in[7];
    const float* gcn_out_b= (const float*)d_in[8];
    const float* Wq       = (const float*)d_in[9];
    const float* Wk       = (const float*)d_in[10];
    const float* Wv       = (const float*)d_in[11];
    const float* Wo       = (const float*)d_in[12];
    const float* ln2_w    = (const float*)d_in[13];
    const float* ln2_b    = (const float*)d_in[14];
    const float* ln3_w    = (const float*)d_in[15];
    const float* ln3_b    = (const float*)d_in[16];
    const float* geglu_w  = (const float*)d_in[17];
    const float* geglu_b  = (const float*)d_in[18];
    const float* ffo_w    = (const float*)d_in[19];
    const float* ffo_b    = (const float*)d_in[20];
    float* out = (float*)d_out;

    float *h, *b1, *b2, *b3, *kb, *vb, *f, *u;
    __nv_bfloat16 *bt0, *bt1;
    cudaGetSymbolAddress((void**)&h,  g_h);
    cudaGetSymbolAddress((void**)&b1, g_b1);
    cudaGetSymbolAddress((void**)&b2, g_b2);
    cudaGetSymbolAddress((void**)&b3, g_b3);
    cudaGetSymbolAddress((void**)&kb, g_kb);
    cudaGetSymbolAddress((void**)&vb, g_vb);
    cudaGetSymbolAddress((void**)&f,  g_f);
    cudaGetSymbolAddress((void**)&u,  g_u);
    cudaGetSymbolAddress((void**)&bt0, g_bt0);
    cudaGetSymbolAddress((void**)&bt1, g_bt1);

    cudaFuncSetAttribute(attn_kernel,
                         cudaFuncAttributeMaxDynamicSharedMemorySize, 131072);
    cudaFuncSetAttribute(mm_gemm,
                         cudaFuncAttributeMaxDynamicSharedMemorySize, MM_SMEM);

    // ---- weight transpose + bf16 split (offsets in elements) ----
    const size_t OFF_GIN = 0, OFF_GOUT = 262144, OFF_L0 = 524288, PER_L = 4194304;
    auto T = [&](const float* W, size_t off, int K, int N) {
        wsplit<<<dim3(N/32, K/32), dim3(32, 8)>>>(W, bt0 + off, bt1 + off, K, N);
    };
    T(gcn_in_w,  OFF_GIN,  512, 512);
    T(gcn_out_w, OFF_GOUT, 512, 512);
    for (int l = 0; l < LL; l++) {
        size_t base = OFF_L0 + (size_t)l * PER_L;
        T(Wq + (size_t)l*262144,       base,           512, 512);
        T(Wk + (size_t)l*262144,       base + 262144,  512, 512);
        T(Wv + (size_t)l*262144,       base + 524288,  512, 512);
        T(Wo + (size_t)l*262144,       base + 786432,  512, 512);
        T(geglu_w + (size_t)l*2097152, base + 1048576, 512, 4096);
        T(ffo_w + (size_t)l*1048576,   base + 3145728, 2048, 512);
    }
    auto G = [&](const float* A, size_t off, float* C, int M, int N, int K,
                 const float* bias, const float* add) {
        mm_gemm<<<dim3(N/128, M/128), 256, MM_SMEM>>>(
            A, bt0 + off, bt1 + off, C, M, N, K, bias, add);
    };

    // ---- edge index normalize + degrees ----
    detect_kernel<<<1, 256>>>((const int*)edges);
    convert_kernel<<<(2*EE + 255) / 256, 256>>>(edges);
    zero_stats<<<NN / 256, 256>>>();
    deg_kernel<<<EE / 256, 256>>>();
    dinv_kernel<<<NN / 256, 256>>>();

    // ---- BatchNorm ----
    bn_partial<<<dim3(2, 16), 256>>>(x);
    bn_apply<<<(NN * DD) / 256, 256>>>(x, bn_w, bn_b, b1);

    // ---- GCN in ----
    G(b1, OFF_GIN, b2, NN, DD, DD, nullptr, nullptr);
    gcn_init<<<(NN * DD) / 256, 256>>>(b2, gcn_in_b, nullptr, h);
    gcn_scatter<<<EE / 8, 256>>>(b2, h);

    // ---- transformer layers ----
    for (int i = 0; i < LL; i++) {
        size_t base = OFF_L0 + (size_t)i * PER_L;
        ln_kernel<<<NN / 8, 256>>>(h, ln2_w + i*DD, ln2_b + i*DD, b1);
        G(b1,   base,           b2, NN,      512, DD, nullptr, nullptr);
        G(cond, base + 262144,  kb, BSZ*MM,  512, DD, nullptr, nullptr);
        G(cond, base + 524288,  vb, BSZ*MM,  512, DD, nullptr, nullptr);
        attn_kernel<<<dim3(HH, BSZ), 256, 131072>>>(b2, kb, vb, b3);
        G(b3,   base + 786432,  h,  NN,      DD,  512, nullptr, h);
        ln_kernel<<<NN / 8, 256>>>(h, ln3_w + i*DD, ln3_b + i*DD, b1);
        G(b1,   base + 1048576, u,  NN,     4096, DD, geglu_b + (size_t)i*4096, nullptr);
        geglu_kernel<<<(NN * 2048 / 4) / 256, 256>>>();
        G(f,    base + 3145728, h,  NN,      DD, 2048, ffo_b + i*DD, h);
    }

    // ---- GCN out + residual ----
    G(h, OFF_GOUT, b1, NN, DD, DD, nullptr, nullptr);
    gcn_init<<<(NN * DD) / 256, 256>>>(b1, gcn_out_b, x, out);
    gcn_scatter<<<EE / 8, 256>>>(b1, out);
}

// round 6
// speedup vs baseline: 2.0608x; 1.3498x over previous
#include <cuda_runtime.h>
#include <cuda_bf16.h>
#include <math.h>
#include <stdint.h>

#define NN 16384
#define DD 512
#define BSZ 16
#define MM 256
#define HH 8
#define DHH 64
#define LL 4
#define EE 262144
#define EPSV 1e-5f

// ---------------- scratch (static device globals) ---------------------------
__device__ float g_h [(size_t)NN*DD];
__device__ float g_b1[(size_t)NN*DD];   // also used as bf16 hi/lo planes
__device__ float g_b2[(size_t)NN*DD];
__device__ float g_b3[(size_t)NN*DD];   // attn out planes
__device__ float g_kb[(size_t)BSZ*MM*DD];
__device__ float g_vb[(size_t)BSZ*MM*DD];
__device__ float g_u [(size_t)NN*4096];
__device__ float g_f [(size_t)NN*2048]; // geglu out planes (2 x bf16)
__device__ __nv_bfloat16 g_cs[(size_t)2*BSZ*MM*DD]; // cond planes
__device__ float g_deg [NN];
__device__ float g_dinv[NN];
__device__ int   g_edge[2*EE];
__device__ int   g_flag;
__device__ float g_sum  [DD];
__device__ float g_sumsq[DD];
#define WT_TOTAL 17301504ULL
__device__ __nv_bfloat16 g_bt0[WT_TOTAL];
__device__ __nv_bfloat16 g_bt1[WT_TOTAL];

// ======================= helpers =============================================
__device__ __forceinline__ uint32_t smem_u32(const void* p) {
    uint32_t a;
    asm("{ .reg .u64 t; cvta.to.shared.u64 t, %1; cvt.u32.u64 %0, t; }"
        : "=r"(a) : "l"(p));
    return a;
}
// 64B-row swizzle: chunk (16B) xored with row bits
__device__ __forceinline__ uint32_t sw64(int row, int c) {
    return ((uint32_t)row << 6) + (((uint32_t)(c ^ ((row >> 1) & 3))) << 4);
}

#define LDSM_X4(r, addr) \
    asm volatile("ldmatrix.sync.aligned.m8n8.x4.shared.b16 {%0,%1,%2,%3}, [%4];" \
        : "=r"((r)[0]), "=r"((r)[1]), "=r"((r)[2]), "=r"((r)[3]) : "r"(addr))

__device__ __forceinline__ void mma16816(float* c, const uint32_t* a, const uint32_t* b) {
    asm volatile("mma.sync.aligned.m16n8k16.row.col.f32.bf16.bf16.f32 "
        "{%0,%1,%2,%3}, {%4,%5,%6,%7}, {%8,%9}, {%0,%1,%2,%3};"
        : "+f"(c[0]), "+f"(c[1]), "+f"(c[2]), "+f"(c[3])
        : "r"(a[0]), "r"(a[1]), "r"(a[2]), "r"(a[3]), "r"(b[0]), "r"(b[1]));
}

#define CP_ASYNC16(dst, src) \
    asm volatile("cp.async.cg.shared.global [%0], [%1], 16;" :: "r"(dst), "l"(src))
#define CP_COMMIT()  asm volatile("cp.async.commit_group;" ::: "memory")
#define CP_WAIT2()   asm volatile("cp.async.wait_group 2;" ::: "memory")
#define CP_WAIT0()   asm volatile("cp.async.wait_group 0;" ::: "memory")

__device__ __forceinline__ void split2(float a, float b, uint32_t& hi, uint32_t& lo) {
    __nv_bfloat16 ha = __float2bfloat16(a), hb = __float2bfloat16(b);
    __nv_bfloat162 H = __halves2bfloat162(ha, hb);
    __nv_bfloat162 L = __halves2bfloat162(
        __float2bfloat16(a - __bfloat162float(ha)),
        __float2bfloat16(b - __bfloat162float(hb)));
    hi = *(uint32_t*)&H; lo = *(uint32_t*)&L;
}

// ---------------- weight transpose + bf16 split -----------------------------
__global__ void wsplit(const float* __restrict__ W, __nv_bfloat16* __restrict__ O0,
                       __nv_bfloat16* __restrict__ O1, int K, int N) {
    __shared__ float t[32][33];
    int bn = blockIdx.x * 32, bk = blockIdx.y * 32;
    int tx = threadIdx.x, ty = threadIdx.y;
    for (int i = ty; i < 32; i += 8)
        t[i][tx] = W[(size_t)(bk + i) * N + bn + tx];
    __syncthreads();
    for (int i = ty; i < 32; i += 8) {
        float v = t[tx][i];
        __nv_bfloat16 h0 = __float2bfloat16(v);
        float r = v - __bfloat162float(h0);
        size_t o = (size_t)(bn + i) * K + bk + tx;
        O0[o] = h0;
        O1[o] = __float2bfloat16(r);
    }
}

// ---------------- fp32 -> split-bf16 planes (generic) ------------------------
__global__ void fsplit(const float* __restrict__ in, __nv_bfloat16* __restrict__ hi,
                       __nv_bfloat16* __restrict__ lo) {
    size_t i = (size_t)blockIdx.x * 256 + threadIdx.x;  // float4 index
    float4 v = ((const float4*)in)[i];
    uint32_t h0, h1, l0, l1;
    split2(v.x, v.y, h0, l0);
    split2(v.z, v.w, h1, l1);
    ((uint2*)hi)[i] = make_uint2(h0, h1);
    ((uint2*)lo)[i] = make_uint2(l0, l1);
}

// ---------------- HMMA split-bf16 GEMM ---------------------------------------
// C[M,N] = A[M,K]*W[K,N]; A pre-split planes A0/A1 [M][K] bf16; W pre-split
// B0/B1 [N][K] bf16. CTA 128x256, 8 warps (2m x 4n), warp 64x64, BK=32, 4 stages.
// Stage 48KB: A0@0(8K), A1@8K, B0@16K(16K), B1@32K. Total 192KB.
#define MM_SMEM 196608
#define STG 49152

__device__ __forceinline__ void mm_issue(
    const __nv_bfloat16* __restrict__ A0, const __nv_bfloat16* __restrict__ A1,
    const __nv_bfloat16* __restrict__ B0, const __nv_bfloat16* __restrict__ B1,
    uint32_t sb, int stage, int bm, int bn, int K, int kc, int tid)
{
    uint32_t a0b = sb + stage * STG, a1b = a0b + 8192;
    uint32_t b0b = a0b + 16384, b1b = a0b + 32768;
#pragma unroll
    for (int i = 0; i < 2; i++) {
        int idx = i * 256 + tid;
        int r = idx >> 2, c = idx & 3;
        uint32_t d = sw64(r, c);
        size_t src = (size_t)(bm + r) * K + kc * 32 + c * 8;
        CP_ASYNC16(a0b + d, A0 + src);
        CP_ASYNC16(a1b + d, A1 + src);
    }
#pragma unroll
    for (int i = 0; i < 4; i++) {
        int idx = i * 256 + tid;
        int r = idx >> 2, c = idx & 3;
        uint32_t d = sw64(r, c);
        size_t src = (size_t)(bn + r) * K + kc * 32 + c * 8;
        CP_ASYNC16(b0b + d, B0 + src);
        CP_ASYNC16(b1b + d, B1 + src);
    }
}

__global__ __launch_bounds__(256, 1)
void mm_gemm(const __nv_bfloat16* __restrict__ A0, const __nv_bfloat16* __restrict__ A1,
             const __nv_bfloat16* __restrict__ B0, const __nv_bfloat16* __restrict__ B1,
             float* __restrict__ C, int M, int N, int K,
             const float* __restrict__ bias, const float* __restrict__ add)
{
    extern __shared__ char smem[];
    uint32_t sb = smem_u32(smem);
    const int tid = threadIdx.x, wid = tid >> 5, lane = tid & 31;
    const int bm = blockIdx.y * 128, bn = blockIdx.x * 256;
    const int wm = wid >> 2, wn = wid & 3;
    const int nch = K >> 5;

    float acc[4][8][4];
#pragma unroll
    for (int i = 0; i < 4; i++)
#pragma unroll
        for (int j = 0; j < 8; j++)
#pragma unroll
            for (int k = 0; k < 4; k++) acc[i][j][k] = 0.f;

    mm_issue(A0, A1, B0, B1, sb, 0, bm, bn, K, 0, tid); CP_COMMIT();
    mm_issue(A0, A1, B0, B1, sb, 1, bm, bn, K, 1, tid); CP_COMMIT();
    mm_issue(A0, A1, B0, B1, sb, 2, bm, bn, K, 2, tid); CP_COMMIT();

    for (int kc = 0; kc < nch; kc++) {
        const int p = kc & 3;
        const uint32_t stA0 = sb + p * STG, stA1 = stA0 + 8192;
        const uint32_t stB0 = stA0 + 16384, stB1 = stA0 + 32768;
        CP_WAIT2();
        __syncthreads();

#pragma unroll
        for (int s = 0; s < 2; s++) {
            uint32_t a0[4][4], a1[4][4];
#pragma unroll
            for (int mf = 0; mf < 4; mf++) {
                int row = wm * 64 + mf * 16 + (lane & 15);
                int c = 2 * s + (lane >> 4);
                uint32_t off = sw64(row, c);
                LDSM_X4(a0[mf], stA0 + off);
                LDSM_X4(a1[mf], stA1 + off);
            }
#pragma unroll
            for (int g = 0; g < 4; g++) {
                int row = wn * 64 + g * 16 + ((lane >> 4) << 3) + (lane & 7);
                int c = 2 * s + ((lane >> 3) & 1);
                uint32_t off = sw64(row, c);
                uint32_t rb0[4], rb1[4];
                LDSM_X4(rb0, stB0 + off);
                LDSM_X4(rb1, stB1 + off);
#pragma unroll
                for (int mf = 0; mf < 4; mf++) {
                    mma16816(acc[mf][2*g],   a0[mf], rb0);
                    mma16816(acc[mf][2*g+1], a0[mf], rb0 + 2);
                    mma16816(acc[mf][2*g],   a1[mf], rb0);
                    mma16816(acc[mf][2*g+1], a1[mf], rb0 + 2);
                    mma16816(acc[mf][2*g],   a0[mf], rb1);
                    mma16816(acc[mf][2*g+1], a0[mf], rb1 + 2);
                }
            }
        }
        if (kc + 3 < nch) {
            mm_issue(A0, A1, B0, B1, sb, (kc + 3) & 3, bm, bn, K, kc + 3, tid);
        }
        CP_COMMIT();
    }

    // epilogue
#pragma unroll
    for (int mf = 0; mf < 4; mf++) {
#pragma unroll
        for (int ng = 0; ng < 8; ng++) {
            int r0 = bm + wm * 64 + mf * 16 + (lane >> 2);
            int c0 = bn + wn * 64 + ng * 8 + ((lane & 3) << 1);
            float2 v0 = make_float2(acc[mf][ng][0], acc[mf][ng][1]);
            float2 v1 = make_float2(acc[mf][ng][2], acc[mf][ng][3]);
            if (bias) {
                float2 bb = *(const float2*)(bias + c0);
                v0.x += bb.x; v0.y += bb.y; v1.x += bb.x; v1.y += bb.y;
            }
            if (add) {
                float2 a0v = *(const float2*)(add + (size_t)r0 * N + c0);
                float2 a1v = *(const float2*)(add + (size_t)(r0 + 8) * N + c0);
                v0.x += a0v.x; v0.y += a0v.y; v1.x += a1v.x; v1.y += a1v.y;
            }
            *(float2*)(C + (size_t)r0 * N + c0) = v0;
            *(float2*)(C + (size_t)(r0 + 8) * N + c0) = v1;
        }
    }
}

// ---------------- edge-index dtype detect + convert ------------------------
__global__ void detect_kernel(const int* __restrict__ e32) {
    __shared__ int any;
    if (threadIdx.x == 0) any = 0;
    __syncthreads();
    int bad = 0;
    for (int i = threadIdx.x; i < 4096; i += 256)
        if (e32[2*i + 1] != 0) bad = 1;
    if (bad) any = 1;
    __syncthreads();
    if (threadIdx.x == 0) g_flag = (any == 0) ? 1 : 0;
}

__global__ void convert_kernel(const void* __restrict__ e) {
    int i = blockIdx.x * 256 + threadIdx.x;
    if (i >= 2*EE) return;
    g_edge[i] = g_flag ? (int)((const long long*)e)[i] : ((const int*)e)[i];
}

__global__ void zero_stats() {
    int i = blockIdx.x * 256 + threadIdx.x;
    if (i < NN) g_deg[i] = 0.f;
    if (i < DD) { g_sum[i] = 0.f; g_sumsq[i] = 0.f; }
}

__global__ void deg_kernel() {
    int e = blockIdx.x * 256 + threadIdx.x;
    if (e < EE) atomicAdd(&g_deg[g_edge[EE + e]], 1.f);
}

__global__ void dinv_kernel() {
    int i = blockIdx.x * 256 + threadIdx.x;
    if (i < NN) g_dinv[i] = rsqrtf(g_deg[i] + 1.f);
}

// ---------------- BatchNorm --------------------------------------------------
__global__ void bn_partial(const float* __restrict__ x) {
    int col = blockIdx.x * 256 + threadIdx.x;
    int r0  = blockIdx.y * 1024;
    float s = 0.f, ss = 0.f;
    for (int r = r0; r < r0 + 1024; r++) {
        float v = x[(size_t)r * DD + col];
        s += v; ss += v * v;
    }
    atomicAdd(&g_sum[col], s);
    atomicAdd(&g_sumsq[col], ss);
}

// BN apply -> split planes
__global__ void bn_apply(const float* __restrict__ x, const float* __restrict__ w,
                         const float* __restrict__ b, __nv_bfloat16* __restrict__ hi,
                         __nv_bfloat16* __restrict__ lo) {
    size_t i4 = (size_t)blockIdx.x * 256 + threadIdx.x;
    int c4 = (int)(i4 & 127) * 4;
    float4 xv = ((const float4*)x)[i4];
    float4 sm = *(const float4*)(g_sum + c4);
    float4 sq = *(const float4*)(g_sumsq + c4);
    float4 wv = *(const float4*)(w + c4);
    float4 bv = *(const float4*)(b + c4);
    float4 o;
    {
        float mu = sm.x / NN, var = sq.x / NN - mu*mu;
        o.x = (xv.x - mu) * rsqrtf(var + EPSV) * wv.x + bv.x;
        mu = sm.y / NN; var = sq.y / NN - mu*mu;
        o.y = (xv.y - mu) * rsqrtf(var + EPSV) * wv.y + bv.y;
        mu = sm.z / NN; var = sq.z / NN - mu*mu;
        o.z = (xv.z - mu) * rsqrtf(var + EPSV) * wv.z + bv.z;
        mu = sm.w / NN; var = sq.w / NN - mu*mu;
        o.w = (xv.w - mu) * rsqrtf(var + EPSV) * wv.w + bv.w;
    }
    uint32_t h0, h1, l0, l1;
    split2(o.x, o.y, h0, l0);
    split2(o.z, o.w, h1, l1);
    ((uint2*)hi)[i4] = make_uint2(h0, h1);
    ((uint2*)lo)[i4] = make_uint2(l0, l1);
}

// ---------------- LayerNorm -> split planes ----------------------------------
__global__ void ln_kernel(const float* __restrict__ x, const float* __restrict__ w,
                          const float* __restrict__ b, __nv_bfloat16* __restrict__ hi,
                          __nv_bfloat16* __restrict__ lo) {
    int warp = (blockIdx.x * blockDim.x + threadIdx.x) >> 5;
    int lane = threadIdx.x & 31;
    if (warp >= NN) return;
    const float4* xr = (const float4*)(x + (size_t)warp * DD);
    float4 v[4];
    float s = 0.f, ss = 0.f;
#pragma unroll
    for (int i = 0; i < 4; i++) {
        v[i] = xr[lane + 32*i];
        s  += v[i].x + v[i].y + v[i].z + v[i].w;
        ss += v[i].x*v[i].x + v[i].y*v[i].y + v[i].z*v[i].z + v[i].w*v[i].w;
    }
#pragma unroll
    for (int o = 16; o; o >>= 1) {
        s  += __shfl_xor_sync(0xffffffffu, s,  o);
        ss += __shfl_xor_sync(0xffffffffu, ss, o);
    }
    float mean = s * (1.f / DD);
    float var  = ss * (1.f / DD) - mean * mean;
    float rs   = rsqrtf(var + EPSV);
    uint2* hr = (uint2*)(hi + (size_t)warp * DD);
    uint2* lr = (uint2*)(lo + (size_t)warp * DD);
    const float4* wr = (const float4*)w;
    const float4* br = (const float4*)b;
#pragma unroll
    for (int i = 0; i < 4; i++) {
        float4 wv = wr[lane + 32*i], bv = br[lane + 32*i], o4;
        o4.x = (v[i].x - mean) * rs * wv.x + bv.x;
        o4.y = (v[i].y - mean) * rs * wv.y + bv.y;
        o4.z = (v[i].z - mean) * rs * wv.z + bv.z;
        o4.w = (v[i].w - mean) * rs * wv.w + bv.w;
        uint32_t h0, h1, l0, l1;
        split2(o4.x, o4.y, h0, l0);
        split2(o4.z, o4.w, h1, l1);
        hr[lane + 32*i] = make_uint2(h0, h1);
        lr[lane + 32*i] = make_uint2(l0, l1);
    }
}

// ---------------- GCN scatter ------------------------------------------------
__global__ void gcn_init(const float* __restrict__ hw, const float* __restrict__ bias,
                         const float* __restrict__ extra, float* __restrict__ out) {
    size_t i = (size_t)blockIdx.x * 256 + threadIdx.x;
    int r = (int)(i >> 9), c = (int)(i & 511);
    float dv = g_dinv[r];
    float v = hw[i] * dv * dv + bias[c];
    if (extra) v += extra[i];
    out[i] = v;
}

__global__ void gcn_scatter(const float* __restrict__ hw, float* __restrict__ out) {
    int wid  = (blockIdx.x * blockDim.x + threadIdx.x) >> 5;
    int lane = threadIdx.x & 31;
    if (wid >= EE) return;
    int s = g_edge[wid], d = g_edge[EE + wid];
    float w = g_dinv[s] * g_dinv[d];
    const float* hp = hw + (size_t)s * DD;
    float* op = out + (size_t)d * DD;
#pragma unroll
    for (int i = 0; i < 16; i++) {
        int c = lane + 32 * i;
        atomicAdd(op + c, hp[c] * w);
    }
}

// ---------------- fused cross-attention (single pass, split output) ----------
__global__ __launch_bounds__(256) void attn_kernel(
    const float* __restrict__ Q, const float* __restrict__ Kc,
    const float* __restrict__ Vc, __nv_bfloat16* __restrict__ Ohi,
    __nv_bfloat16* __restrict__ Olo)
{
    extern __shared__ float smemf[];
    float* Ks = smemf;
    float* Vs = smemf + 256 * 64;
    const int h = blockIdx.x, b = blockIdx.y;
    const int tid = threadIdx.x;
    for (int i = tid; i < 256 * 16; i += 256) {
        int m = i >> 4, d4 = (i & 15) << 2;
        size_t g = (size_t)(b * MM + m) * DD + h * DHH + d4;
        *(float4*)&Ks[m * 64 + d4] = *(const float4*)(Kc + g);
        *(float4*)&Vs[m * 64 + d4] = *(const float4*)(Vc + g);
    }
    __syncthreads();
    const float scale = 0.125f;
    for (int r = 0; r < 4; r++) {
        int n = r * 256 + tid;
        const float* qp = Q + (size_t)(b * 1024 + n) * DD + h * DHH;
        float q[64];
#pragma unroll
        for (int i = 0; i < 16; i++) *(float4*)&q[i*4] = *(const float4*)(qp + i*4);
        float mx = -1e30f, s = 0.f;
        float o[64];
#pragma unroll
        for (int d = 0; d < 64; d++) o[d] = 0.f;
        for (int m = 0; m < 256; m++) {
            float dot = 0.f;
#pragma unroll
            for (int d = 0; d < 64; d++) dot = fmaf(q[d], Ks[m*64 + d], dot);
            dot *= scale;
            if (dot > mx) {
                float corr = __expf(mx - dot);
                s = s * corr + 1.f;
                mx = dot;
#pragma unroll
                for (int d = 0; d < 64; d++)
                    o[d] = fmaf(o[d], corr, Vs[m*64 + d]);
            } else {
                float w = __expf(dot - mx);
                s += w;
#pragma unroll
                for (int d = 0; d < 64; d++) o[d] = fmaf(w, Vs[m*64 + d], o[d]);
            }
        }
        float inv = 1.f / s;
        size_t ob = (size_t)(b * 1024 + n) * DD + h * DHH;
        uint2* hp = (uint2*)(Ohi + ob);
        uint2* lp = (uint2*)(Olo + ob);
#pragma unroll
        for (int i = 0; i < 16; i++) {
            uint32_t h0, h1, l0, l1;
            split2(o[i*4+0] * inv, o[i*4+1] * inv, h0, l0);
            split2(o[i*4+2] * inv, o[i*4+3] * inv, h1, l1);
            hp[i] = make_uint2(h0, h1);
            lp[i] = make_uint2(l0, l1);
        }
    }
}

// ---------------- GEGLU -> split planes --------------------------------------
__global__ void geglu_kernel(__nv_bfloat16* __restrict__ fhi,
                             __nv_bfloat16* __restrict__ flo) {
    size_t i = (size_t)blockIdx.x * 256 + threadIdx.x;  // float4 idx over NN*2048/4
    int r = (int)(i >> 9), c4 = (int)(i & 511);
    const float4* up = (const float4*)g_u;
    float4 val  = up[(size_t)r * 1024 + c4];
    float4 gate = up[(size_t)r * 1024 + 512 + c4];
    float4 o;
    o.x = val.x * 0.5f * gate.x * (1.f + erff(gate.x * 0.70710678f));
    o.y = val.y * 0.5f * gate.y * (1.f + erff(gate.y * 0.70710678f));
    o.z = val.z * 0.5f * gate.z * (1.f + erff(gate.z * 0.70710678f));
    o.w = val.w * 0.5f * gate.w * (1.f + erff(gate.w * 0.70710678f));
    uint32_t h0, h1, l0, l1;
    split2(o.x, o.y, h0, l0);
    split2(o.z, o.w, h1, l1);
    ((uint2*)fhi)[i] = make_uint2(h0, h1);
    ((uint2*)flo)[i] = make_uint2(l0, l1);
}

// ---------------- host orchestration ----------------------------------------
extern "C" void kernel_launch(void* const* d_in, const int* in_sizes, int n_in,
                              void* d_out, int out_size)
{
    const float* x        = (const float*)d_in[0];
    const void*  edges    = d_in[1];
    const float* cond     = (const float*)d_in[2];
    const float* bn_w     = (const float*)d_in[3];
    const float* bn_b     = (const float*)d_in[4];
    const float* gcn_in_w = (const float*)d_in[5];
    const float* gcn_in_b = (const float*)d_in[6];
    const float* gcn_out_w= (const float*)d_in[7];
    const float* gcn_out_b= (const float*)d_in[8];
    const float* Wq       = (const float*)d_in[9];
    const float* Wk       = (const float*)d_in[10];
    const float* Wv       = (const float*)d_in[11];
    const float* Wo       = (const float*)d_in[12];
    const float* ln2_w    = (const float*)d_in[13];
    const float* ln2_b    = (const float*)d_in[14];
    const float* ln3_w    = (const float*)d_in[15];
    const float* ln3_b    = (const float*)d_in[16];
    const float* geglu_w  = (const float*)d_in[17];
    const float* geglu_b  = (const float*)d_in[18];
    const float* ffo_w    = (const float*)d_in[19];
    const float* ffo_b    = (const float*)d_in[20];
    float* out = (float*)d_out;

    float *h, *b1, *b2, *b3, *kb, *vb, *f, *u;
    __nv_bfloat16 *bt0, *bt1, *cs;
    cudaGetSymbolAddress((void**)&h,  g_h);
    cudaGetSymbolAddress((void**)&b1, g_b1);
    cudaGetSymbolAddress((void**)&b2, g_b2);
    cudaGetSymbolAddress((void**)&b3, g_b3);
    cudaGetSymbolAddress((void**)&kb, g_kb);
    cudaGetSymbolAddress((void**)&vb, g_vb);
    cudaGetSymbolAddress((void**)&f,  g_f);
    cudaGetSymbolAddress((void**)&u,  g_u);
    cudaGetSymbolAddress((void**)&bt0, g_bt0);
    cudaGetSymbolAddress((void**)&bt1, g_bt1);
    cudaGetSymbolAddress((void**)&cs, g_cs);

    // plane views (hi at base, lo at +M*K)
    __nv_bfloat16* b1h = (__nv_bfloat16*)b1;
    __nv_bfloat16* b1l = b1h + (size_t)NN*DD;
    __nv_bfloat16* b3h = (__nv_bfloat16*)b3;
    __nv_bfloat16* b3l = b3h + (size_t)NN*DD;
    __nv_bfloat16* fh  = (__nv_bfloat16*)f;
    __nv_bfloat16* fl  = fh + (size_t)NN*2048;
    __nv_bfloat16* csh = cs;
    __nv_bfloat16* csl = cs + (size_t)BSZ*MM*DD;

    cudaFuncSetAttribute(attn_kernel,
                         cudaFuncAttributeMaxDynamicSharedMemorySize, 131072);
    cudaFuncSetAttribute(mm_gemm,
                         cudaFuncAttributeMaxDynamicSharedMemorySize, MM_SMEM);

    // ---- weight transpose + bf16 split ----
    const size_t OFF_GIN = 0, OFF_GOUT = 262144, OFF_L0 = 524288, PER_L = 4194304;
    auto T = [&](const float* W, size_t off, int K, int N) {
        wsplit<<<dim3(N/32, K/32), dim3(32, 8)>>>(W, bt0 + off, bt1 + off, K, N);
    };
    T(gcn_in_w,  OFF_GIN,  512, 512);
    T(gcn_out_w, OFF_GOUT, 512, 512);
    for (int l = 0; l < LL; l++) {
        size_t base = OFF_L0 + (size_t)l * PER_L;
        T(Wq + (size_t)l*262144,       base,           512, 512);
        T(Wk + (size_t)l*262144,       base + 262144,  512, 512);
        T(Wv + (size_t)l*262144,       base + 524288,  512, 512);
        T(Wo + (size_t)l*262144,       base + 786432,  512, 512);
        T(geglu_w + (size_t)l*2097152, base + 1048576, 512, 4096);
        T(ffo_w + (size_t)l*1048576,   base + 3145728, 2048, 512);
    }
    auto G = [&](const __nv_bfloat16* Ah, const __nv_bfloat16* Al, size_t off,
                 float* C, int M, int N, int K, const float* bias, const float* add) {
        mm_gemm<<<dim3(N/256, M/128), 256, MM_SMEM>>>(
            Ah, Al, bt0 + off, bt1 + off, C, M, N, K, bias, add);
    };

    // ---- edges / degrees ----
    detect_kernel<<<1, 256>>>((const int*)edges);
    convert_kernel<<<(2*EE + 255) / 256, 256>>>(edges);
    zero_stats<<<NN / 256, 256>>>();
    deg_kernel<<<EE / 256, 256>>>();
    dinv_kernel<<<NN / 256, 256>>>();

    // ---- cond split (once) ----
    fsplit<<<(BSZ*MM*DD/4) / 256, 256>>>(cond, csh, csl);

    // ---- BatchNorm -> b1 planes ----
    bn_partial<<<dim3(2, 16), 256>>>(x);
    bn_apply<<<(NN * DD / 4) / 256, 256>>>(x, bn_w, bn_b, b1h, b1l);

    // ---- GCN in ----
    G(b1h, b1l, OFF_GIN, b2, NN, DD, DD, nullptr, nullptr);
    gcn_init<<<(NN * DD) / 256, 256>>>(b2, gcn_in_b, nullptr, h);
    gcn_scatter<<<EE / 8, 256>>>(b2, h);

    // ---- transformer layers ----
    for (int i = 0; i < LL; i++) {
        size_t base = OFF_L0 + (size_t)i * PER_L;
        ln_kernel<<<NN / 8, 256>>>(h, ln2_w + i*DD, ln2_b + i*DD, b1h, b1l);
        G(b1h, b1l, base,           b2, NN,     512, DD, nullptr, nullptr);
        G(csh, csl, base + 262144,  kb, BSZ*MM, 512, DD, nullptr, nullptr);
        G(csh, csl, base + 524288,  vb, BSZ*MM, 512, DD, nullptr, nullptr);
        attn_kernel<<<dim3(HH, BSZ), 256, 131072>>>(b2, kb, vb, b3h, b3l);
        G(b3h, b3l, base + 786432,  h,  NN,     DD,  512, nullptr, h);
        ln_kernel<<<NN / 8, 256>>>(h, ln3_w + i*DD, ln3_b + i*DD, b1h, b1l);
        G(b1h, b1l, base + 1048576, u,  NN,    4096, DD, geglu_b + (size_t)i*4096, nullptr);
        geglu_kernel<<<(NN * 2048 / 4) / 256, 256>>>(fh, fl);
        G(fh, fl,   base + 3145728, h,  NN,     DD, 2048, ffo_b + i*DD, h);
    }

    // ---- GCN out + residual ----
    fsplit<<<(NN*DD/4) / 256, 256>>>(h, b1h, b1l);
    G(b1h, b1l, OFF_GOUT, b2, NN, DD, DD, nullptr, nullptr);
    gcn_init<<<(NN * DD) / 256, 256>>>(b2, gcn_out_b, x, out);
    gcn_scatter<<<EE / 8, 256>>>(b2, out);
}

// round 9
// speedup vs baseline: 2.1503x; 1.0434x over previous
#include <cuda_runtime.h>
#include <cuda_bf16.h>
#include <math.h>
#include <stdint.h>

#define NN 16384
#define DD 512
#define BSZ 16
#define MM 256
#define HH 8
#define DHH 64
#define LL 4
#define EE 262144
#define EPSV 1e-5f

// ---------------- scratch (static device globals) ---------------------------
__device__ float g_h [(size_t)NN*DD];
__device__ float g_b1[(size_t)NN*DD];
__device__ float g_b2[(size_t)NN*DD];
__device__ float g_b3[(size_t)NN*DD];
__device__ float g_kb[(size_t)BSZ*MM*DD];
__device__ float g_vb[(size_t)BSZ*MM*DD];
__device__ float g_u [(size_t)NN*4096];
__device__ float g_f [(size_t)NN*2048];
__device__ __nv_bfloat16 g_cs[(size_t)2*BSZ*MM*DD];
__device__ float g_deg [NN];
__device__ float g_dinv[NN];
__device__ int   g_edge[2*EE];
__device__ int   g_flag;
__device__ float g_sum  [DD];
__device__ float g_sumsq[DD];
#define WT_TOTAL 17301504ULL
__device__ __nv_bfloat16 g_bt0[WT_TOTAL];
__device__ __nv_bfloat16 g_bt1[WT_TOTAL];

// ======================= helpers =============================================
__device__ __forceinline__ uint32_t smem_u32(const void* p) {
    uint32_t a;
    asm("{ .reg .u64 t; cvta.to.shared.u64 t, %1; cvt.u32.u64 %0, t; }"
        : "=r"(a) : "l"(p));
    return a;
}
__device__ __forceinline__ uint32_t sw64(int row, int c) {
    return ((uint32_t)row << 6) + (((uint32_t)(c ^ ((row >> 1) & 3))) << 4);
}

#define LDSM_X4(r, addr) \
    asm volatile("ldmatrix.sync.aligned.m8n8.x4.shared.b16 {%0,%1,%2,%3}, [%4];" \
        : "=r"((r)[0]), "=r"((r)[1]), "=r"((r)[2]), "=r"((r)[3]) : "r"(addr))

__device__ __forceinline__ void mma16816(float* c, const uint32_t* a, const uint32_t* b) {
    asm volatile("mma.sync.aligned.m16n8k16.row.col.f32.bf16.bf16.f32 "
        "{%0,%1,%2,%3}, {%4,%5,%6,%7}, {%8,%9}, {%0,%1,%2,%3};"
        : "+f"(c[0]), "+f"(c[1]), "+f"(c[2]), "+f"(c[3])
        : "r"(a[0]), "r"(a[1]), "r"(a[2]), "r"(a[3]), "r"(b[0]), "r"(b[1]));
}

#define CP_ASYNC16(dst, src) \
    asm volatile("cp.async.cg.shared.global [%0], [%1], 16;" :: "r"(dst), "l"(src))
#define CP_COMMIT()  asm volatile("cp.async.commit_group;" ::: "memory")
#define CP_WAIT1()   asm volatile("cp.async.wait_group 1;" ::: "memory")

__device__ __forceinline__ void split2(float a, float b, uint32_t& hi, uint32_t& lo) {
    __nv_bfloat16 ha = __float2bfloat16(a), hb = __float2bfloat16(b);
    __nv_bfloat162 H = __halves2bfloat162(ha, hb);
    __nv_bfloat162 L = __halves2bfloat162(
        __float2bfloat16(a - __bfloat162float(ha)),
        __float2bfloat16(b - __bfloat162float(hb)));
    hi = *(uint32_t*)&H; lo = *(uint32_t*)&L;
}

// ---------------- weight transpose + bf16 split (z-batched over layers) ------
__global__ void wsplit(const float* __restrict__ W, __nv_bfloat16* __restrict__ O0,
                       __nv_bfloat16* __restrict__ O1, int K, int N,
                       size_t wstride, size_t ostride) {
    __shared__ float t[32][33];
    W  += (size_t)blockIdx.z * wstride;
    O0 += (size_t)blockIdx.z * ostride;
    O1 += (size_t)blockIdx.z * ostride;
    int bn = blockIdx.x * 32, bk = blockIdx.y * 32;
    int tx = threadIdx.x, ty = threadIdx.y;
    for (int i = ty; i < 32; i += 8)
        t[i][tx] = W[(size_t)(bk + i) * N + bn + tx];
    __syncthreads();
    for (int i = ty; i < 32; i += 8) {
        float v = t[tx][i];
        __nv_bfloat16 h0 = __float2bfloat16(v);
        float r = v - __bfloat162float(h0);
        size_t o = (size_t)(bn + i) * K + bk + tx;
        O0[o] = h0;
        O1[o] = __float2bfloat16(r);
    }
}

// ---------------- fp32 -> split-bf16 planes ----------------------------------
__global__ void fsplit(const float* __restrict__ in, __nv_bfloat16* __restrict__ hi,
                       __nv_bfloat16* __restrict__ lo) {
    size_t i = (size_t)blockIdx.x * 256 + threadIdx.x;
    float4 v = ((const float4*)in)[i];
    uint32_t h0, h1, l0, l1;
    split2(v.x, v.y, h0, l0);
    split2(v.z, v.w, h1, l1);
    ((uint2*)hi)[i] = make_uint2(h0, h1);
    ((uint2*)lo)[i] = make_uint2(l0, l1);
}

// ---------------- HMMA split-bf16 GEMM, occupancy 2 --------------------------
// CTA 128x128, 8 warps (2m x 4n), warp 64x32, BK=32, 3 stages x 32KB = 96KB.
#define MM_SMEM 98304
#define STG 32768

__device__ __forceinline__ void mm_issue(
    const __nv_bfloat16* __restrict__ A0, const __nv_bfloat16* __restrict__ A1,
    const __nv_bfloat16* __restrict__ B0, const __nv_bfloat16* __restrict__ B1,
    uint32_t sb, int stage, int bm, int bn, int K, int kc, int tid)
{
    uint32_t a0b = sb + stage * STG, a1b = a0b + 8192;
    uint32_t b0b = a0b + 16384, b1b = a0b + 24576;
#pragma unroll
    for (int i = 0; i < 2; i++) {
        int idx = i * 256 + tid;
        int r = idx >> 2, c = idx & 3;
        uint32_t d = sw64(r, c);
        size_t sa = (size_t)(bm + r) * K + kc * 32 + c * 8;
        size_t sbx = (size_t)(bn + r) * K + kc * 32 + c * 8;
        CP_ASYNC16(a0b + d, A0 + sa);
        CP_ASYNC16(a1b + d, A1 + sa);
        CP_ASYNC16(b0b + d, B0 + sbx);
        CP_ASYNC16(b1b + d, B1 + sbx);
    }
}

__global__ __launch_bounds__(256, 2)
void mm_gemm(const __nv_bfloat16* __restrict__ A0, const __nv_bfloat16* __restrict__ A1,
             const __nv_bfloat16* __restrict__ B0, const __nv_bfloat16* __restrict__ B1,
             float* __restrict__ C, int M, int N, int K,
             const float* __restrict__ bias, const float* __restrict__ add)
{
    extern __shared__ char smem[];
    uint32_t sb = smem_u32(smem);
    const int tid = threadIdx.x, wid = tid >> 5, lane = tid & 31;
    const int bm = blockIdx.y * 128, bn = blockIdx.x * 128;
    const int wm = wid >> 2, wn = wid & 3;
    const int nch = K >> 5;

    float acc[4][4][4];
#pragma unroll
    for (int i = 0; i < 4; i++)
#pragma unroll
        for (int j = 0; j < 4; j++)
#pragma unroll
            for (int k = 0; k < 4; k++) acc[i][j][k] = 0.f;

    mm_issue(A0, A1, B0, B1, sb, 0, bm, bn, K, 0, tid); CP_COMMIT();
    mm_issue(A0, A1, B0, B1, sb, 1, bm, bn, K, 1, tid); CP_COMMIT();

    int pc = 0, pi = 2;
    for (int kc = 0; kc < nch; kc++) {
        CP_WAIT1();
        __syncthreads();
        if (kc + 2 < nch)
            mm_issue(A0, A1, B0, B1, sb, pi, bm, bn, K, kc + 2, tid);
        CP_COMMIT();

        const uint32_t stA0 = sb + pc * STG, stA1 = stA0 + 8192;
        const uint32_t stB0 = stA0 + 16384, stB1 = stA0 + 24576;
#pragma unroll
        for (int s = 0; s < 2; s++) {
            uint32_t rb0[2][4], rb1[2][4];
#pragma unroll
            for (int g = 0; g < 2; g++) {
                int row = wn * 32 + g * 16 + ((lane >> 4) << 3) + (lane & 7);
                int c = 2 * s + ((lane >> 3) & 1);
                uint32_t off = sw64(row, c);
                LDSM_X4(rb0[g], stB0 + off);
                LDSM_X4(rb1[g], stB1 + off);
            }
            uint32_t a[4][4];
            int arow = wm * 64 + (lane & 15);
            int ac = 2 * s + (lane >> 4);
#pragma unroll
            for (int mf = 0; mf < 4; mf++)
                LDSM_X4(a[mf], stA0 + sw64(arow + mf * 16, ac));
#pragma unroll
            for (int mf = 0; mf < 4; mf++)
#pragma unroll
                for (int g = 0; g < 2; g++) {
                    mma16816(acc[mf][2*g],   a[mf], rb0[g]);
                    mma16816(acc[mf][2*g+1], a[mf], rb0[g] + 2);
                    mma16816(acc[mf][2*g],   a[mf], rb1[g]);
                    mma16816(acc[mf][2*g+1], a[mf], rb1[g] + 2);
                }
#pragma unroll
            for (int mf = 0; mf < 4; mf++)
                LDSM_X4(a[mf], stA1 + sw64(arow + mf * 16, ac));
#pragma unroll
            for (int mf = 0; mf < 4; mf++)
#pragma unroll
                for (int g = 0; g < 2; g++) {
                    mma16816(acc[mf][2*g],   a[mf], rb0[g]);
                    mma16816(acc[mf][2*g+1], a[mf], rb0[g] + 2);
                }
        }
        pc = (pc == 2) ? 0 : pc + 1;
        pi = (pi == 2) ? 0 : pi + 1;
    }

    // epilogue
#pragma unroll
    for (int mf = 0; mf < 4; mf++) {
#pragma unroll
        for (int ng = 0; ng < 4; ng++) {
            int r0 = bm + wm * 64 + mf * 16 + (lane >> 2);
            int c0 = bn + wn * 32 + ng * 8 + ((lane & 3) << 1);
            float2 v0 = make_float2(acc[mf][ng][0], acc[mf][ng][1]);
            float2 v1 = make_float2(acc[mf][ng][2], acc[mf][ng][3]);
            if (bias) {
                float2 bb = *(const float2*)(bias + c0);
                v0.x += bb.x; v0.y += bb.y; v1.x += bb.x; v1.y += bb.y;
            }
            if (add) {
                float2 a0v = *(const float2*)(add + (size_t)r0 * N + c0);
                float2 a1v = *(const float2*)(add + (size_t)(r0 + 8) * N + c0);
                v0.x += a0v.x; v0.y += a0v.y; v1.x += a1v.x; v1.y += a1v.y;
            }
            *(float2*)(C + (size_t)r0 * N + c0) = v0;
            *(float2*)(C + (size_t)(r0 + 8) * N + c0) = v1;
        }
    }
}

// ---------------- edge-index dtype detect + convert ------------------------
__global__ void detect_kernel(const int* __restrict__ e32) {
    __shared__ int any;
    if (threadIdx.x == 0) any = 0;
    __syncthreads();
    int bad = 0;
    for (int i = threadIdx.x; i < 4096; i += 256)
        if (e32[2*i + 1] != 0) bad = 1;
    if (bad) any = 1;
    __syncthreads();
    if (threadIdx.x == 0) g_flag = (any == 0) ? 1 : 0;
}

__global__ void convert_kernel(const void* __restrict__ e) {
    int i = blockIdx.x * 256 + threadIdx.x;
    if (i >= 2*EE) return;
    g_edge[i] = g_flag ? (int)((const long long*)e)[i] : ((const int*)e)[i];
}

__global__ void zero_stats() {
    int i = blockIdx.x * 256 + threadIdx.x;
    if (i < NN) g_deg[i] = 0.f;
    if (i < DD) { g_sum[i] = 0.f; g_sumsq[i] = 0.f; }
}

__global__ void deg_kernel() {
    int e = blockIdx.x * 256 + threadIdx.x;
    if (e < EE) atomicAdd(&g_deg[g_edge[EE + e]], 1.f);
}

__global__ void dinv_kernel() {
    int i = blockIdx.x * 256 + threadIdx.x;
    if (i < NN) g_dinv[i] = rsqrtf(g_deg[i] + 1.f);
}

// ---------------- BatchNorm --------------------------------------------------
__global__ void bn_partial(const float* __restrict__ x) {
    int col = blockIdx.x * 256 + threadIdx.x;
    int r0  = blockIdx.y * 1024;
    float s = 0.f, ss = 0.f;
    for (int r = r0; r < r0 + 1024; r++) {
        float v = x[(size_t)r * DD + col];
        s += v; ss += v * v;
    }
    atomicAdd(&g_sum[col], s);
    atomicAdd(&g_sumsq[col], ss);
}

__global__ void bn_apply(const float* __restrict__ x, const float* __restrict__ w,
                         const float* __restrict__ b, __nv_bfloat16* __restrict__ hi,
                         __nv_bfloat16* __restrict__ lo) {
    size_t i4 = (size_t)blockIdx.x * 256 + threadIdx.x;
    int c4 = (int)(i4 & 127) * 4;
    float4 xv = ((const float4*)x)[i4];
    float4 sm = *(const float4*)(g_sum + c4);
    float4 sq = *(const float4*)(g_sumsq + c4);
    float4 wv = *(const float4*)(w + c4);
    float4 bv = *(const float4*)(b + c4);
    float4 o;
    {
        float mu = sm.x / NN, var = sq.x / NN - mu*mu;
        o.x = (xv.x - mu) * rsqrtf(var + EPSV) * wv.x + bv.x;
        mu = sm.y / NN; var = sq.y / NN - mu*mu;
        o.y = (xv.y - mu) * rsqrtf(var + EPSV) * wv.y + bv.y;
        mu = sm.z / NN; var = sq.z / NN - mu*mu;
        o.z = (xv.z - mu) * rsqrtf(var + EPSV) * wv.z + bv.z;
        mu = sm.w / NN; var = sq.w / NN - mu*mu;
        o.w = (xv.w - mu) * rsqrtf(var + EPSV) * wv.w + bv.w;
    }
    uint32_t h0, h1, l0, l1;
    split2(o.x, o.y, h0, l0);
    split2(o.z, o.w, h1, l1);
    ((uint2*)hi)[i4] = make_uint2(h0, h1);
    ((uint2*)lo)[i4] = make_uint2(l0, l1);
}

// ---------------- LayerNorm -> split planes ----------------------------------
__global__ void ln_kernel(const float* __restrict__ x, const float* __restrict__ w,
                          const float* __restrict__ b, __nv_bfloat16* __restrict__ hi,
                          __nv_bfloat16* __restrict__ lo) {
    int warp = (blockIdx.x * blockDim.x + threadIdx.x) >> 5;
    int lane = threadIdx.x & 31;
    if (warp >= NN) return;
    const float4* xr = (const float4*)(x + (size_t)warp * DD);
    float4 v[4];
    float s = 0.f, ss = 0.f;
#pragma unroll
    for (int i = 0; i < 4; i++) {
        v[i] = xr[lane + 32*i];
        s  += v[i].x + v[i].y + v[i].z + v[i].w;
        ss += v[i].x*v[i].x + v[i].y*v[i].y + v[i].z*v[i].z + v[i].w*v[i].w;
    }
#pragma unroll
    for (int o = 16; o; o >>= 1) {
        s  += __shfl_xor_sync(0xffffffffu, s,  o);
        ss += __shfl_xor_sync(0xffffffffu, ss, o);
    }
    float mean = s * (1.f / DD);
    float var  = ss * (1.f / DD) - mean * mean;
    float rs   = rsqrtf(var + EPSV);
    uint2* hr = (uint2*)(hi + (size_t)warp * DD);
    uint2* lr = (uint2*)(lo + (size_t)warp * DD);
    const float4* wr = (const float4*)w;
    const float4* br = (const float4*)b;
#pragma unroll
    for (int i = 0; i < 4; i++) {
        float4 wv = wr[lane + 32*i], bv = br[lane + 32*i], o4;
        o4.x = (v[i].x - mean) * rs * wv.x + bv.x;
        o4.y = (v[i].y - mean) * rs * wv.y + bv.y;
        o4.z = (v[i].z - mean) * rs * wv.z + bv.z;
        o4.w = (v[i].w - mean) * rs * wv.w + bv.w;
        uint32_t h0, h1, l0, l1;
        split2(o4.x, o4.y, h0, l0);
        split2(o4.z, o4.w, h1, l1);
        hr[lane + 32*i] = make_uint2(h0, h1);
        lr[lane + 32*i] = make_uint2(l0, l1);
    }
}

// ---------------- GCN scatter ------------------------------------------------
__global__ void gcn_init(const float* __restrict__ hw, const float* __restrict__ bias,
                         const float* __restrict__ extra, float* __restrict__ out) {
    size_t i = (size_t)blockIdx.x * 256 + threadIdx.x;
    int r = (int)(i >> 9), c = (int)(i & 511);
    float dv = g_dinv[r];
    float v = hw[i] * dv * dv + bias[c];
    if (extra) v += extra[i];
    out[i] = v;
}

__global__ void gcn_scatter(const float* __restrict__ hw, float* __restrict__ out) {
    int wid  = (blockIdx.x * blockDim.x + threadIdx.x) >> 5;
    int lane = threadIdx.x & 31;
    if (wid >= EE) return;
    int s = g_edge[wid], d = g_edge[EE + wid];
    float w = g_dinv[s] * g_dinv[d];
    const float4* hp = (const float4*)(hw + (size_t)s * DD);
    float4* op = (float4*)(out + (size_t)d * DD);
#pragma unroll
    for (int i = 0; i < 4; i++) {
        int c = lane + 32 * i;
        float4 v = hp[c];
        v.x *= w; v.y *= w; v.z *= w; v.w *= w;
        atomicAdd(op + c, v);
    }
}

// ---------------- fused cross-attention (single pass, split output) ----------
__global__ __launch_bounds__(256) void attn_kernel(
    const float* __restrict__ Q, const float* __restrict__ Kc,
    const float* __restrict__ Vc, __nv_bfloat16* __restrict__ Ohi,
    __nv_bfloat16* __restrict__ Olo)
{
    extern __shared__ float smemf[];
    float* Ks = smemf;
    float* Vs = smemf + 256 * 64;
    const int h = blockIdx.x, b = blockIdx.y;
    const int tid = threadIdx.x;
    for (int i = tid; i < 256 * 16; i += 256) {
        int m = i >> 4, d4 = (i & 15) << 2;
        size_t g = (size_t)(b * MM + m) * DD + h * DHH + d4;
        *(float4*)&Ks[m * 64 + d4] = *(const float4*)(Kc + g);
        *(float4*)&Vs[m * 64 + d4] = *(const float4*)(Vc + g);
    }
    __syncthreads();
    const float scale = 0.125f;
    for (int r = 0; r < 4; r++) {
        int n = r * 256 + tid;
        const float* qp = Q + (size_t)(b * 1024 + n) * DD + h * DHH;
        float q[64];
#pragma unroll
        for (int i = 0; i < 16; i++) *(float4*)&q[i*4] = *(const float4*)(qp + i*4);
        float mx = -1e30f, s = 0.f;
        float o[64];
#pragma unroll
        for (int d = 0; d < 64; d++) o[d] = 0.f;
        for (int m = 0; m < 256; m++) {
            float dot = 0.f;
#pragma unroll
            for (int d = 0; d < 64; d++) dot = fmaf(q[d], Ks[m*64 + d], dot);
            dot *= scale;
            if (dot > mx) {
                float corr = __expf(mx - dot);
                s = s * corr + 1.f;
                mx = dot;
#pragma unroll
                for (int d = 0; d < 64; d++)
                    o[d] = fmaf(o[d], corr, Vs[m*64 + d]);
            } else {
                float w = __expf(dot - mx);
                s += w;
#pragma unroll
                for (int d = 0; d < 64; d++) o[d] = fmaf(w, Vs[m*64 + d], o[d]);
            }
        }
        float inv = 1.f / s;
        size_t ob = (size_t)(b * 1024 + n) * DD + h * DHH;
        uint2* hp = (uint2*)(Ohi + ob);
        uint2* lp = (uint2*)(Olo + ob);
#pragma unroll
        for (int i = 0; i < 16; i++) {
            uint32_t h0, h1, l0, l1;
            split2(o[i*4+0] * inv, o[i*4+1] * inv, h0, l0);
            split2(o[i*4+2] * inv, o[i*4+3] * inv, h1, l1);
            hp[i] = make_uint2(h0, h1);
            lp[i] = make_uint2(l0, l1);
        }
    }
}

// ---------------- GEGLU -> split planes --------------------------------------
__global__ void geglu_kernel(__nv_bfloat16* __restrict__ fhi,
                             __nv_bfloat16* __restrict__ flo) {
    size_t i = (size_t)blockIdx.x * 256 + threadIdx.x;
    int r = (int)(i >> 9), c4 = (int)(i & 511);
    const float4* up = (const float4*)g_u;
    float4 val  = up[(size_t)r * 1024 + c4];
    float4 gate = up[(size_t)r * 1024 + 512 + c4];
    float4 o;
    o.x = val.x * 0.5f * gate.x * (1.f + erff(gate.x * 0.70710678f));
    o.y = val.y * 0.5f * gate.y * (1.f + erff(gate.y * 0.70710678f));
    o.z = val.z * 0.5f * gate.z * (1.f + erff(gate.z * 0.70710678f));
    o.w = val.w * 0.5f * gate.w * (1.f + erff(gate.w * 0.70710678f));
    uint32_t h0, h1, l0, l1;
    split2(o.x, o.y, h0, l0);
    split2(o.z, o.w, h1, l1);
    ((uint2*)fhi)[i] = make_uint2(h0, h1);
    ((uint2*)flo)[i] = make_uint2(l0, l1);
}

// ---------------- host orchestration ----------------------------------------
extern "C" void kernel_launch(void* const* d_in, const int* in_sizes, int n_in,
                              void* d_out, int out_size)
{
    const float* x        = (const float*)d_in[0];
    const void*  edges    = d_in[1];
    const float* cond     = (const float*)d_in[2];
    const float* bn_w     = (const float*)d_in[3];
    const float* bn_b     = (const float*)d_in[4];
    const float* gcn_in_w = (const float*)d_in[5];
    const float* gcn_in_b = (const float*)d_in[6];
    const float* gcn_out_w= (const float*)d_in[7];
    const float* gcn_out_b= (const float*)d_in[8];
    const float* Wq       = (const float*)d_in[9];
    const float* Wk       = (const float*)d_in[10];
    const float* Wv       = (const float*)d_in[11];
    const float* Wo       = (const float*)d_in[12];
    const float* ln2_w    = (const float*)d_in[13];
    const float* ln2_b    = (const float*)d_in[14];
    const float* ln3_w    = (const float*)d_in[15];
    const float* ln3_b    = (const float*)d_in[16];
    const float* geglu_w  = (const float*)d_in[17];
    const float* geglu_b  = (const float*)d_in[18];
    const float* ffo_w    = (const float*)d_in[19];
    const float* ffo_b    = (const float*)d_in[20];
    float* out = (float*)d_out;

    float *h, *b1, *b2, *b3, *kb, *vb, *f, *u;
    __nv_bfloat16 *bt0, *bt1, *cs;
    cudaGetSymbolAddress((void**)&h,  g_h);
    cudaGetSymbolAddress((void**)&b1, g_b1);
    cudaGetSymbolAddress((void**)&b2, g_b2);
    cudaGetSymbolAddress((void**)&b3, g_b3);
    cudaGetSymbolAddress((void**)&kb, g_kb);
    cudaGetSymbolAddress((void**)&vb, g_vb);
    cudaGetSymbolAddress((void**)&f,  g_f);
    cudaGetSymbolAddress((void**)&u,  g_u);
    cudaGetSymbolAddress((void**)&bt0, g_bt0);
    cudaGetSymbolAddress((void**)&bt1, g_bt1);
    cudaGetSymbolAddress((void**)&cs, g_cs);

    __nv_bfloat16* b1h = (__nv_bfloat16*)b1;
    __nv_bfloat16* b1l = b1h + (size_t)NN*DD;
    __nv_bfloat16* b3h = (__nv_bfloat16*)b3;
    __nv_bfloat16* b3l = b3h + (size_t)NN*DD;
    __nv_bfloat16* fh  = (__nv_bfloat16*)f;
    __nv_bfloat16* fl  = fh + (size_t)NN*2048;
    __nv_bfloat16* csh = cs;
    __nv_bfloat16* csl = cs + (size_t)BSZ*MM*DD;

    cudaFuncSetAttribute(attn_kernel,
                         cudaFuncAttributeMaxDynamicSharedMemorySize, 131072);
    cudaFuncSetAttribute(mm_gemm,
                         cudaFuncAttributeMaxDynamicSharedMemorySize, MM_SMEM);

    // ---- weight transpose + bf16 split (z-batched over 4 layers) ----
    const size_t OFF_GIN = 0, OFF_GOUT = 262144, OFF_L0 = 524288, PER_L = 4194304;
    wsplit<<<dim3(16, 16, 1), dim3(32, 8)>>>(gcn_in_w,  bt0 + OFF_GIN,  bt1 + OFF_GIN,  512, 512, 0, 0);
    wsplit<<<dim3(16, 16, 1), dim3(32, 8)>>>(gcn_out_w, bt0 + OFF_GOUT, bt1 + OFF_GOUT, 512, 512, 0, 0);
    wsplit<<<dim3(16, 16, 4), dim3(32, 8)>>>(Wq, bt0 + OFF_L0,          bt1 + OFF_L0,          512, 512, 262144, PER_L);
    wsplit<<<dim3(16, 16, 4), dim3(32, 8)>>>(Wk, bt0 + OFF_L0 + 262144, bt1 + OFF_L0 + 262144, 512, 512, 262144, PER_L);
    wsplit<<<dim3(16, 16, 4), dim3(32, 8)>>>(Wv, bt0 + OFF_L0 + 524288, bt1 + OFF_L0 + 524288, 512, 512, 262144, PER_L);
    wsplit<<<dim3(16, 16, 4), dim3(32, 8)>>>(Wo, bt0 + OFF_L0 + 786432, bt1 + OFF_L0 + 786432, 512, 512, 262144, PER_L);
    wsplit<<<dim3(128, 16, 4), dim3(32, 8)>>>(geglu_w, bt0 + OFF_L0 + 1048576, bt1 + OFF_L0 + 1048576, 512, 4096, 2097152, PER_L);
    wsplit<<<dim3(16, 64, 4), dim3(32, 8)>>>(ffo_w, bt0 + OFF_L0 + 3145728, bt1 + OFF_L0 + 3145728, 2048, 512, 1048576, PER_L);

    auto G = [&](const __nv_bfloat16* Ah, const __nv_bfloat16* Al, size_t off,
                 float* C, int M, int N, int K, const float* bias, const float* add) {
        mm_gemm<<<dim3(N/128, M/128), 256, MM_SMEM>>>(
            Ah, Al, bt0 + off, bt1 + off, C, M, N, K, bias, add);
    };

    // ---- edges / degrees ----
    detect_kernel<<<1, 256>>>((const int*)edges);
    convert_kernel<<<(2*EE + 255) / 256, 256>>>(edges);
    zero_stats<<<NN / 256, 256>>>();
    deg_kernel<<<EE / 256, 256>>>();
    dinv_kernel<<<NN / 256, 256>>>();

    // ---- cond split (once) ----
    fsplit<<<(BSZ*MM*DD/4) / 256, 256>>>(cond, csh, csl);

    // ---- BatchNorm -> b1 planes ----
    bn_partial<<<dim3(2, 16), 256>>>(x);
    bn_apply<<<(NN * DD / 4) / 256, 256>>>(x, bn_w, bn_b, b1h, b1l);

    // ---- GCN in ----
    G(b1h, b1l, OFF_GIN, b2, NN, DD, DD, nullptr, nullptr);
    gcn_init<<<(NN * DD) / 256, 256>>>(b2, gcn_in_b, nullptr, h);
    gcn_scatter<<<EE / 8, 256>>>(b2, h);

    // ---- transformer layers ----
    for (int i = 0; i < LL; i++) {
        size_t base = OFF_L0 + (size_t)i * PER_L;
        ln_kernel<<<NN / 8, 256>>>(h, ln2_w + i*DD, ln2_b + i*DD, b1h, b1l);
        G(b1h, b1l, base,           b2, NN,     512, DD, nullptr, nullptr);
        G(csh, csl, base + 262144,  kb, BSZ*MM, 512, DD, nullptr, nullptr);
        G(csh, csl, base + 524288,  vb, BSZ*MM, 512, DD, nullptr, nullptr);
        attn_kernel<<<dim3(HH, BSZ), 256, 131072>>>(b2, kb, vb, b3h, b3l);
        G(b3h, b3l, base + 786432,  h,  NN,     DD,  512, nullptr, h);
        ln_kernel<<<NN / 8, 256>>>(h, ln3_w + i*DD, ln3_b + i*DD, b1h, b1l);
        G(b1h, b1l, base + 1048576, u,  NN,    4096, DD, geglu_b + (size_t)i*4096, nullptr);
        geglu_kernel<<<(NN * 2048 / 4) / 256, 256>>>(fh, fl);
        G(fh, fl,   base + 3145728, h,  NN,     DD, 2048, ffo_b + i*DD, h);
    }

    // ---- GCN out + residual ----
    fsplit<<<(NN*DD/4) / 256, 256>>>(h, b1h, b1l);
    G(b1h, b1l, OFF_GOUT, b2, NN, DD, DD, nullptr, nullptr);
    gcn_init<<<(NN * DD) / 256, 256>>>(b2, gcn_out_b, x, out);
    gcn_scatter<<<EE / 8, 256>>>(b2, out);
}

// round 10
// speedup vs baseline: 2.6669x; 1.2403x over previous
#include <cuda_runtime.h>
#include <cuda_bf16.h>
#include <math.h>
#include <stdint.h>

#define NN 16384
#define DD 512
#define BSZ 16
#define MM 256
#define HH 8
#define DHH 64
#define LL 4
#define EE 262144
#define EPSV 1e-5f

// ---------------- scratch (static device globals) ---------------------------
__device__ float g_h [(size_t)NN*DD];
__device__ float g_b1[(size_t)NN*DD];
__device__ float g_b2[(size_t)NN*DD];
__device__ float g_b3[(size_t)NN*DD];
__device__ float g_kb[(size_t)BSZ*MM*DD];
__device__ float g_vb[(size_t)BSZ*MM*DD];
__device__ float g_u [(size_t)NN*4096];
__device__ float g_f [(size_t)NN*2048];
__device__ __nv_bfloat16 g_cs[(size_t)2*BSZ*MM*DD];
__device__ float g_deg [NN];
__device__ float g_dinv[NN];
__device__ int   g_edge[2*EE];
__device__ int   g_flag;
__device__ float g_sum  [DD];
__device__ float g_sumsq[DD];
#define WT_TOTAL 17301504ULL
__device__ __nv_bfloat16 g_bt0[WT_TOTAL];
__device__ __nv_bfloat16 g_bt1[WT_TOTAL];

// ======================= helpers =============================================
__device__ __forceinline__ uint32_t smem_u32(const void* p) {
    uint32_t a;
    asm("{ .reg .u64 t; cvta.to.shared.u64 t, %1; cvt.u32.u64 %0, t; }"
        : "=r"(a) : "l"(p));
    return a;
}
__device__ __forceinline__ uint32_t sw64(int row, int c) {
    return ((uint32_t)row << 6) + (((uint32_t)(c ^ ((row >> 1) & 3))) << 4);
}
// 128B-row swizzle (64 bf16 per row), chunk = 16B
__device__ __forceinline__ uint32_t asw(int row, int ch) {
    return ((uint32_t)row << 7) + (((uint32_t)(ch ^ (row & 7))) << 4);
}

#define LDSM_X4(r, addr) \
    asm volatile("ldmatrix.sync.aligned.m8n8.x4.shared.b16 {%0,%1,%2,%3}, [%4];" \
        : "=r"((r)[0]), "=r"((r)[1]), "=r"((r)[2]), "=r"((r)[3]) : "r"(addr))
#define LDSM_X4_T(r, addr) \
    asm volatile("ldmatrix.sync.aligned.m8n8.x4.trans.shared.b16 {%0,%1,%2,%3}, [%4];" \
        : "=r"((r)[0]), "=r"((r)[1]), "=r"((r)[2]), "=r"((r)[3]) : "r"(addr))

__device__ __forceinline__ void mma16816(float* c, const uint32_t* a, const uint32_t* b) {
    asm volatile("mma.sync.aligned.m16n8k16.row.col.f32.bf16.bf16.f32 "
        "{%0,%1,%2,%3}, {%4,%5,%6,%7}, {%8,%9}, {%0,%1,%2,%3};"
        : "+f"(c[0]), "+f"(c[1]), "+f"(c[2]), "+f"(c[3])
        : "r"(a[0]), "r"(a[1]), "r"(a[2]), "r"(a[3]), "r"(b[0]), "r"(b[1]));
}

#define CP_ASYNC16(dst, src) \
    asm volatile("cp.async.cg.shared.global [%0], [%1], 16;" :: "r"(dst), "l"(src))
#define CP_COMMIT()  asm volatile("cp.async.commit_group;" ::: "memory")
#define CP_WAIT1()   asm volatile("cp.async.wait_group 1;" ::: "memory")

__device__ __forceinline__ void split2(float a, float b, uint32_t& hi, uint32_t& lo) {
    __nv_bfloat16 ha = __float2bfloat16(a), hb = __float2bfloat16(b);
    __nv_bfloat162 H = __halves2bfloat162(ha, hb);
    __nv_bfloat162 L = __halves2bfloat162(
        __float2bfloat16(a - __bfloat162float(ha)),
        __float2bfloat16(b - __bfloat162float(hb)));
    hi = *(uint32_t*)&H; lo = *(uint32_t*)&L;
}

// ---------------- weight transpose + bf16 split (z-batched over layers) ------
__global__ void wsplit(const float* __restrict__ W, __nv_bfloat16* __restrict__ O0,
                       __nv_bfloat16* __restrict__ O1, int K, int N,
                       size_t wstride, size_t ostride) {
    __shared__ float t[32][33];
    W  += (size_t)blockIdx.z * wstride;
    O0 += (size_t)blockIdx.z * ostride;
    O1 += (size_t)blockIdx.z * ostride;
    int bn = blockIdx.x * 32, bk = blockIdx.y * 32;
    int tx = threadIdx.x, ty = threadIdx.y;
    for (int i = ty; i < 32; i += 8)
        t[i][tx] = W[(size_t)(bk + i) * N + bn + tx];
    __syncthreads();
    for (int i = ty; i < 32; i += 8) {
        float v = t[tx][i];
        __nv_bfloat16 h0 = __float2bfloat16(v);
        float r = v - __bfloat162float(h0);
        size_t o = (size_t)(bn + i) * K + bk + tx;
        O0[o] = h0;
        O1[o] = __float2bfloat16(r);
    }
}

// ---------------- fp32 -> split-bf16 planes ----------------------------------
__global__ void fsplit(const float* __restrict__ in, __nv_bfloat16* __restrict__ hi,
                       __nv_bfloat16* __restrict__ lo) {
    size_t i = (size_t)blockIdx.x * 256 + threadIdx.x;
    float4 v = ((const float4*)in)[i];
    uint32_t h0, h1, l0, l1;
    split2(v.x, v.y, h0, l0);
    split2(v.z, v.w, h1, l1);
    ((uint2*)hi)[i] = make_uint2(h0, h1);
    ((uint2*)lo)[i] = make_uint2(l0, l1);
}

// ---------------- HMMA split-bf16 GEMM, occupancy 2 --------------------------
#define MM_SMEM 98304
#define STG 32768

__device__ __forceinline__ void mm_issue(
    const __nv_bfloat16* __restrict__ A0, const __nv_bfloat16* __restrict__ A1,
    const __nv_bfloat16* __restrict__ B0, const __nv_bfloat16* __restrict__ B1,
    uint32_t sb, int stage, int bm, int bn, int K, int kc, int tid)
{
    uint32_t a0b = sb + stage * STG, a1b = a0b + 8192;
    uint32_t b0b = a0b + 16384, b1b = a0b + 24576;
#pragma unroll
    for (int i = 0; i < 2; i++) {
        int idx = i * 256 + tid;
        int r = idx >> 2, c = idx & 3;
        uint32_t d = sw64(r, c);
        size_t sa = (size_t)(bm + r) * K + kc * 32 + c * 8;
        size_t sbx = (size_t)(bn + r) * K + kc * 32 + c * 8;
        CP_ASYNC16(a0b + d, A0 + sa);
        CP_ASYNC16(a1b + d, A1 + sa);
        CP_ASYNC16(b0b + d, B0 + sbx);
        CP_ASYNC16(b1b + d, B1 + sbx);
    }
}

__global__ __launch_bounds__(256, 2)
void mm_gemm(const __nv_bfloat16* __restrict__ A0, const __nv_bfloat16* __restrict__ A1,
             const __nv_bfloat16* __restrict__ B0, const __nv_bfloat16* __restrict__ B1,
             float* __restrict__ C, int M, int N, int K,
             const float* __restrict__ bias, const float* __restrict__ add)
{
    extern __shared__ char smem[];
    uint32_t sb = smem_u32(smem);
    const int tid = threadIdx.x, wid = tid >> 5, lane = tid & 31;
    const int bm = blockIdx.y * 128, bn = blockIdx.x * 128;
    const int wm = wid >> 2, wn = wid & 3;
    const int nch = K >> 5;

    float acc[4][4][4];
#pragma unroll
    for (int i = 0; i < 4; i++)
#pragma unroll
        for (int j = 0; j < 4; j++)
#pragma unroll
            for (int k = 0; k < 4; k++) acc[i][j][k] = 0.f;

    mm_issue(A0, A1, B0, B1, sb, 0, bm, bn, K, 0, tid); CP_COMMIT();
    mm_issue(A0, A1, B0, B1, sb, 1, bm, bn, K, 1, tid); CP_COMMIT();

    int pc = 0, pi = 2;
    for (int kc = 0; kc < nch; kc++) {
        CP_WAIT1();
        __syncthreads();
        if (kc + 2 < nch)
            mm_issue(A0, A1, B0, B1, sb, pi, bm, bn, K, kc + 2, tid);
        CP_COMMIT();

        const uint32_t stA0 = sb + pc * STG, stA1 = stA0 + 8192;
        const uint32_t stB0 = stA0 + 16384, stB1 = stA0 + 24576;
#pragma unroll
        for (int s = 0; s < 2; s++) {
            uint32_t rb0[2][4], rb1[2][4];
#pragma unroll
            for (int g = 0; g < 2; g++) {
                int row = wn * 32 + g * 16 + ((lane >> 4) << 3) + (lane & 7);
                int c = 2 * s + ((lane >> 3) & 1);
                uint32_t off = sw64(row, c);
                LDSM_X4(rb0[g], stB0 + off);
                LDSM_X4(rb1[g], stB1 + off);
            }
            uint32_t a[4][4];
            int arow = wm * 64 + (lane & 15);
            int ac = 2 * s + (lane >> 4);
#pragma unroll
            for (int mf = 0; mf < 4; mf++)
                LDSM_X4(a[mf], stA0 + sw64(arow + mf * 16, ac));
#pragma unroll
            for (int mf = 0; mf < 4; mf++)
#pragma unroll
                for (int g = 0; g < 2; g++) {
                    mma16816(acc[mf][2*g],   a[mf], rb0[g]);
                    mma16816(acc[mf][2*g+1], a[mf], rb0[g] + 2);
                    mma16816(acc[mf][2*g],   a[mf], rb1[g]);
                    mma16816(acc[mf][2*g+1], a[mf], rb1[g] + 2);
                }
#pragma unroll
            for (int mf = 0; mf < 4; mf++)
                LDSM_X4(a[mf], stA1 + sw64(arow + mf * 16, ac));
#pragma unroll
            for (int mf = 0; mf < 4; mf++)
#pragma unroll
                for (int g = 0; g < 2; g++) {
                    mma16816(acc[mf][2*g],   a[mf], rb0[g]);
                    mma16816(acc[mf][2*g+1], a[mf], rb0[g] + 2);
                }
        }
        pc = (pc == 2) ? 0 : pc + 1;
        pi = (pi == 2) ? 0 : pi + 1;
    }

#pragma unroll
    for (int mf = 0; mf < 4; mf++) {
#pragma unroll
        for (int ng = 0; ng < 4; ng++) {
            int r0 = bm + wm * 64 + mf * 16 + (lane >> 2);
            int c0 = bn + wn * 32 + ng * 8 + ((lane & 3) << 1);
            float2 v0 = make_float2(acc[mf][ng][0], acc[mf][ng][1]);
            float2 v1 = make_float2(acc[mf][ng][2], acc[mf][ng][3]);
            if (bias) {
                float2 bb = *(const float2*)(bias + c0);
                v0.x += bb.x; v0.y += bb.y; v1.x += bb.x; v1.y += bb.y;
            }
            if (add) {
                float2 a0v = *(const float2*)(add + (size_t)r0 * N + c0);
                float2 a1v = *(const float2*)(add + (size_t)(r0 + 8) * N + c0);
                v0.x += a0v.x; v0.y += a0v.y; v1.x += a1v.x; v1.y += a1v.y;
            }
            *(float2*)(C + (size_t)r0 * N + c0) = v0;
            *(float2*)(C + (size_t)(r0 + 8) * N + c0) = v1;
        }
    }
}

// ---------------- edge-index dtype detect + convert ------------------------
__global__ void detect_kernel(const int* __restrict__ e32) {
    __shared__ int any;
    if (threadIdx.x == 0) any = 0;
    __syncthreads();
    int bad = 0;
    for (int i = threadIdx.x; i < 4096; i += 256)
        if (e32[2*i + 1] != 0) bad = 1;
    if (bad) any = 1;
    __syncthreads();
    if (threadIdx.x == 0) g_flag = (any == 0) ? 1 : 0;
}

__global__ void convert_kernel(const void* __restrict__ e) {
    int i = blockIdx.x * 256 + threadIdx.x;
    if (i >= 2*EE) return;
    g_edge[i] = g_flag ? (int)((const long long*)e)[i] : ((const int*)e)[i];
}

__global__ void zero_stats() {
    int i = blockIdx.x * 256 + threadIdx.x;
    if (i < NN) g_deg[i] = 0.f;
    if (i < DD) { g_sum[i] = 0.f; g_sumsq[i] = 0.f; }
}

__global__ void deg_kernel() {
    int e = blockIdx.x * 256 + threadIdx.x;
    if (e < EE) atomicAdd(&g_deg[g_edge[EE + e]], 1.f);
}

__global__ void dinv_kernel() {
    int i = blockIdx.x * 256 + threadIdx.x;
    if (i < NN) g_dinv[i] = rsqrtf(g_deg[i] + 1.f);
}

// ---------------- BatchNorm --------------------------------------------------
__global__ void bn_partial(const float* __restrict__ x) {
    int col = blockIdx.x * 256 + threadIdx.x;
    int r0  = blockIdx.y * 1024;
    float s = 0.f, ss = 0.f;
    for (int r = r0; r < r0 + 1024; r++) {
        float v = x[(size_t)r * DD + col];
        s += v; ss += v * v;
    }
    atomicAdd(&g_sum[col], s);
    atomicAdd(&g_sumsq[col], ss);
}

__global__ void bn_apply(const float* __restrict__ x, const float* __restrict__ w,
                         const float* __restrict__ b, __nv_bfloat16* __restrict__ hi,
                         __nv_bfloat16* __restrict__ lo) {
    size_t i4 = (size_t)blockIdx.x * 256 + threadIdx.x;
    int c4 = (int)(i4 & 127) * 4;
    float4 xv = ((const float4*)x)[i4];
    float4 sm = *(const float4*)(g_sum + c4);
    float4 sq = *(const float4*)(g_sumsq + c4);
    float4 wv = *(const float4*)(w + c4);
    float4 bv = *(const float4*)(b + c4);
    float4 o;
    {
        float mu = sm.x / NN, var = sq.x / NN - mu*mu;
        o.x = (xv.x - mu) * rsqrtf(var + EPSV) * wv.x + bv.x;
        mu = sm.y / NN; var = sq.y / NN - mu*mu;
        o.y = (xv.y - mu) * rsqrtf(var + EPSV) * wv.y + bv.y;
        mu = sm.z / NN; var = sq.z / NN - mu*mu;
        o.z = (xv.z - mu) * rsqrtf(var + EPSV) * wv.z + bv.z;
        mu = sm.w / NN; var = sq.w / NN - mu*mu;
        o.w = (xv.w - mu) * rsqrtf(var + EPSV) * wv.w + bv.w;
    }
    uint32_t h0, h1, l0, l1;
    split2(o.x, o.y, h0, l0);
    split2(o.z, o.w, h1, l1);
    ((uint2*)hi)[i4] = make_uint2(h0, h1);
    ((uint2*)lo)[i4] = make_uint2(l0, l1);
}

// ---------------- LayerNorm -> split planes ----------------------------------
__global__ void ln_kernel(const float* __restrict__ x, const float* __restrict__ w,
                          const float* __restrict__ b, __nv_bfloat16* __restrict__ hi,
                          __nv_bfloat16* __restrict__ lo) {
    int warp = (blockIdx.x * blockDim.x + threadIdx.x) >> 5;
    int lane = threadIdx.x & 31;
    if (warp >= NN) return;
    const float4* xr = (const float4*)(x + (size_t)warp * DD);
    float4 v[4];
    float s = 0.f, ss = 0.f;
#pragma unroll
    for (int i = 0; i < 4; i++) {
        v[i] = xr[lane + 32*i];
        s  += v[i].x + v[i].y + v[i].z + v[i].w;
        ss += v[i].x*v[i].x + v[i].y*v[i].y + v[i].z*v[i].z + v[i].w*v[i].w;
    }
#pragma unroll
    for (int o = 16; o; o >>= 1) {
        s  += __shfl_xor_sync(0xffffffffu, s,  o);
        ss += __shfl_xor_sync(0xffffffffu, ss, o);
    }
    float mean = s * (1.f / DD);
    float var  = ss * (1.f / DD) - mean * mean;
    float rs   = rsqrtf(var + EPSV);
    uint2* hr = (uint2*)(hi + (size_t)warp * DD);
    uint2* lr = (uint2*)(lo + (size_t)warp * DD);
    const float4* wr = (const float4*)w;
    const float4* br = (const float4*)b;
#pragma unroll
    for (int i = 0; i < 4; i++) {
        float4 wv = wr[lane + 32*i], bv = br[lane + 32*i], o4;
        o4.x = (v[i].x - mean) * rs * wv.x + bv.x;
        o4.y = (v[i].y - mean) * rs * wv.y + bv.y;
        o4.z = (v[i].z - mean) * rs * wv.z + bv.z;
        o4.w = (v[i].w - mean) * rs * wv.w + bv.w;
        uint32_t h0, h1, l0, l1;
        split2(o4.x, o4.y, h0, l0);
        split2(o4.z, o4.w, h1, l1);
        hr[lane + 32*i] = make_uint2(h0, h1);
        lr[lane + 32*i] = make_uint2(l0, l1);
    }
}

// ---------------- GCN scatter ------------------------------------------------
__global__ void gcn_init(const float* __restrict__ hw, const float* __restrict__ bias,
                         const float* __restrict__ extra, float* __restrict__ out) {
    size_t i = (size_t)blockIdx.x * 256 + threadIdx.x;
    int r = (int)(i >> 9), c = (int)(i & 511);
    float dv = g_dinv[r];
    float v = hw[i] * dv * dv + bias[c];
    if (extra) v += extra[i];
    out[i] = v;
}

__global__ void gcn_scatter(const float* __restrict__ hw, float* __restrict__ out) {
    int wid  = (blockIdx.x * blockDim.x + threadIdx.x) >> 5;
    int lane = threadIdx.x & 31;
    if (wid >= EE) return;
    int s = g_edge[wid], d = g_edge[EE + wid];
    float w = g_dinv[s] * g_dinv[d];
    const float4* hp = (const float4*)(hw + (size_t)s * DD);
    float4* op = (float4*)(out + (size_t)d * DD);
#pragma unroll
    for (int i = 0; i < 4; i++) {
        int c = lane + 32 * i;
        float4 v = hp[c];
        v.x *= w; v.y *= w; v.z *= w; v.w *= w;
        atomicAdd(op + c, v);
    }
}

// ---------------- HMMA cross-attention (split-bf16, online softmax) ----------
// grid (H, BS, 4): 256 queries x 256 keys x 64 dims per CTA; 8 warps x 32 q.
// smem 192KB: Qhi,Qlo,Khi,Klo,Vhi,Vlo planes [256][64] bf16, 128B rows, asw.
#define ATT_SMEM 196608
#define OQH 0
#define OQL 32768
#define OKH 65536
#define OKL 98304
#define OVH 131072
#define OVL 163840

__global__ __launch_bounds__(256, 1) void attn_kernel(
    const float* __restrict__ Q, const float* __restrict__ Kc,
    const float* __restrict__ Vc, __nv_bfloat16* __restrict__ Ohi,
    __nv_bfloat16* __restrict__ Olo)
{
    extern __shared__ char smem[];
    uint32_t sb = smem_u32(smem);
    const int h = blockIdx.x, b = blockIdx.y, qc = blockIdx.z;
    const int tid = threadIdx.x, wid = tid >> 5, lane = tid & 31;
    const int qbase = b * 1024 + qc * 256;
    const int kbase = b * 256;

    // fill split planes
#pragma unroll 1
    for (int i = 0; i < 8; i++) {
        int idx = i * 256 + tid;
        int row = idx >> 3, ch = idx & 7;
        uint32_t d = asw(row, ch);
        uint32_t h0,h1,h2,h3,l0,l1,l2,l3;
        {
            const float* p = Q + (size_t)(qbase + row) * DD + h * DHH + ch * 8;
            float4 v0 = *(const float4*)p, v1 = *(const float4*)(p + 4);
            split2(v0.x, v0.y, h0, l0); split2(v0.z, v0.w, h1, l1);
            split2(v1.x, v1.y, h2, l2); split2(v1.z, v1.w, h3, l3);
            *(uint4*)(smem + OQH + d) = make_uint4(h0, h1, h2, h3);
            *(uint4*)(smem + OQL + d) = make_uint4(l0, l1, l2, l3);
        }
        {
            const float* p = Kc + (size_t)(kbase + row) * DD + h * DHH + ch * 8;
            float4 v0 = *(const float4*)p, v1 = *(const float4*)(p + 4);
            split2(v0.x, v0.y, h0, l0); split2(v0.z, v0.w, h1, l1);
            split2(v1.x, v1.y, h2, l2); split2(v1.z, v1.w, h3, l3);
            *(uint4*)(smem + OKH + d) = make_uint4(h0, h1, h2, h3);
            *(uint4*)(smem + OKL + d) = make_uint4(l0, l1, l2, l3);
        }
        {
            const float* p = Vc + (size_t)(kbase + row) * DD + h * DHH + ch * 8;
            float4 v0 = *(const float4*)p, v1 = *(const float4*)(p + 4);
            split2(v0.x, v0.y, h0, l0); split2(v0.z, v0.w, h1, l1);
            split2(v1.x, v1.y, h2, l2); split2(v1.z, v1.w, h3, l3);
            *(uint4*)(smem + OVH + d) = make_uint4(h0, h1, h2, h3);
            *(uint4*)(smem + OVL + d) = make_uint4(l0, l1, l2, l3);
        }
    }
    __syncthreads();

    const int wq = wid * 32;
    float oacc[2][8][4];
    float mrow[2][2], srow[2][2];
#pragma unroll
    for (int mf = 0; mf < 2; mf++) {
        mrow[mf][0] = -1e30f; mrow[mf][1] = -1e30f;
        srow[mf][0] = 0.f;    srow[mf][1] = 0.f;
#pragma unroll
        for (int nf = 0; nf < 8; nf++)
#pragma unroll
            for (int e = 0; e < 4; e++) oacc[mf][nf][e] = 0.f;
    }

#pragma unroll 1
    for (int kc4 = 0; kc4 < 4; kc4++) {          // 64-key chunk
        float sacc[2][8][4];
#pragma unroll
        for (int mf = 0; mf < 2; mf++)
#pragma unroll
            for (int nf = 0; nf < 8; nf++)
#pragma unroll
                for (int e = 0; e < 4; e++) sacc[mf][nf][e] = 0.f;

#pragma unroll
        for (int ds = 0; ds < 4; ds++) {          // d16 steps
            uint32_t qh[2][4], ql[2][4];
            int qrow = wq + (lane & 15);
            int qch = 2 * ds + (lane >> 4);
            LDSM_X4(qh[0], sb + OQH + asw(qrow, qch));
            LDSM_X4(qh[1], sb + OQH + asw(qrow + 16, qch));
            LDSM_X4(ql[0], sb + OQL + asw(qrow, qch));
            LDSM_X4(ql[1], sb + OQL + asw(qrow + 16, qch));
#pragma unroll
            for (int g = 0; g < 4; g++) {         // 16-key groups
                int krow = kc4 * 64 + g * 16 + ((lane >> 4) << 3) + (lane & 7);
                int kch = 2 * ds + ((lane >> 3) & 1);
                uint32_t kh[4], kl[4];
                LDSM_X4(kh, sb + OKH + asw(krow, kch));
                LDSM_X4(kl, sb + OKL + asw(krow, kch));
#pragma unroll
                for (int mf = 0; mf < 2; mf++) {
                    mma16816(sacc[mf][2*g],   qh[mf], kh);
                    mma16816(sacc[mf][2*g+1], qh[mf], kh + 2);
                    mma16816(sacc[mf][2*g],   qh[mf], kl);
                    mma16816(sacc[mf][2*g+1], qh[mf], kl + 2);
                    mma16816(sacc[mf][2*g],   ql[mf], kh);
                    mma16816(sacc[mf][2*g+1], ql[mf], kh + 2);
                }
            }
        }

        // online softmax update
#pragma unroll
        for (int mf = 0; mf < 2; mf++) {
            float mx0 = -1e30f, mx1 = -1e30f;
#pragma unroll
            for (int nf = 0; nf < 8; nf++) {
#pragma unroll
                for (int e = 0; e < 4; e++) sacc[mf][nf][e] *= 0.125f;
                mx0 = fmaxf(mx0, fmaxf(sacc[mf][nf][0], sacc[mf][nf][1]));
                mx1 = fmaxf(mx1, fmaxf(sacc[mf][nf][2], sacc[mf][nf][3]));
            }
            mx0 = fmaxf(mx0, __shfl_xor_sync(0xffffffffu, mx0, 1));
            mx0 = fmaxf(mx0, __shfl_xor_sync(0xffffffffu, mx0, 2));
            mx1 = fmaxf(mx1, __shfl_xor_sync(0xffffffffu, mx1, 1));
            mx1 = fmaxf(mx1, __shfl_xor_sync(0xffffffffu, mx1, 2));
            float nm0 = fmaxf(mrow[mf][0], mx0);
            float nm1 = fmaxf(mrow[mf][1], mx1);
            float c0 = __expf(mrow[mf][0] - nm0);
            float c1 = __expf(mrow[mf][1] - nm1);
            mrow[mf][0] = nm0; mrow[mf][1] = nm1;
            srow[mf][0] *= c0; srow[mf][1] *= c1;
#pragma unroll
            for (int nf = 0; nf < 8; nf++) {
                oacc[mf][nf][0] *= c0; oacc[mf][nf][1] *= c0;
                oacc[mf][nf][2] *= c1; oacc[mf][nf][3] *= c1;
                float p0 = __expf(sacc[mf][nf][0] - nm0);
                float p1 = __expf(sacc[mf][nf][1] - nm0);
                float p2 = __expf(sacc[mf][nf][2] - nm1);
                float p3 = __expf(sacc[mf][nf][3] - nm1);
                srow[mf][0] += p0 + p1;
                srow[mf][1] += p2 + p3;
                sacc[mf][nf][0] = p0; sacc[mf][nf][1] = p1;
                sacc[mf][nf][2] = p2; sacc[mf][nf][3] = p3;
            }
        }

        // PV: O += P * V   (P split 2-term, V split 2-term, 3 mma terms)
#pragma unroll
        for (int kk = 0; kk < 4; kk++) {          // k16 steps over keys
            uint32_t p0f[2][4], p1f[2][4];
#pragma unroll
            for (int mf = 0; mf < 2; mf++) {
                const float* s0 = sacc[mf][2*kk];
                const float* s1 = sacc[mf][2*kk+1];
                split2(s0[0], s0[1], p0f[mf][0], p1f[mf][0]);
                split2(s0[2], s0[3], p0f[mf][1], p1f[mf][1]);
                split2(s1[0], s1[1], p0f[mf][2], p1f[mf][2]);
                split2(s1[2], s1[3], p0f[mf][3], p1f[mf][3]);
            }
            int vrow = kc4 * 64 + kk * 16 + (lane & 15);
#pragma unroll
            for (int g = 0; g < 4; g++) {         // d16 blocks
                int vch = 2 * g + (lane >> 4);
                uint32_t vh[4], vl[4];
                LDSM_X4_T(vh, sb + OVH + asw(vrow, vch));
                LDSM_X4_T(vl, sb + OVL + asw(vrow, vch));
#pragma unroll
                for (int mf = 0; mf < 2; mf++) {
                    mma16816(oacc[mf][2*g],   p0f[mf], vh);
                    mma16816(oacc[mf][2*g+1], p0f[mf], vh + 2);
                    mma16816(oacc[mf][2*g],   p0f[mf], vl);
                    mma16816(oacc[mf][2*g+1], p0f[mf], vl + 2);
                    mma16816(oacc[mf][2*g],   p1f[mf], vh);
                    mma16816(oacc[mf][2*g+1], p1f[mf], vh + 2);
                }
            }
        }
    }

    // finalize: normalize rows, write split-bf16 output
#pragma unroll
    for (int mf = 0; mf < 2; mf++) {
        float s0 = srow[mf][0], s1 = srow[mf][1];
        s0 += __shfl_xor_sync(0xffffffffu, s0, 1);
        s0 += __shfl_xor_sync(0xffffffffu, s0, 2);
        s1 += __shfl_xor_sync(0xffffffffu, s1, 1);
        s1 += __shfl_xor_sync(0xffffffffu, s1, 2);
        float i0 = 1.f / s0, i1 = 1.f / s1;
        int r0 = qbase + wq + mf * 16 + (lane >> 2);
#pragma unroll
        for (int nf = 0; nf < 8; nf++) {
            int c = h * DHH + nf * 8 + ((lane & 3) << 1);
            uint32_t hh, lv;
            split2(oacc[mf][nf][0] * i0, oacc[mf][nf][1] * i0, hh, lv);
            *(uint32_t*)(Ohi + (size_t)r0 * DD + c) = hh;
            *(uint32_t*)(Olo + (size_t)r0 * DD + c) = lv;
            split2(oacc[mf][nf][2] * i1, oacc[mf][nf][3] * i1, hh, lv);
            *(uint32_t*)(Ohi + (size_t)(r0 + 8) * DD + c) = hh;
            *(uint32_t*)(Olo + (size_t)(r0 + 8) * DD + c) = lv;
        }
    }
}

// ---------------- GEGLU -> split planes --------------------------------------
__global__ void geglu_kernel(__nv_bfloat16* __restrict__ fhi,
                             __nv_bfloat16* __restrict__ flo) {
    size_t i = (size_t)blockIdx.x * 256 + threadIdx.x;
    int r = (int)(i >> 9), c4 = (int)(i & 511);
    const float4* up = (const float4*)g_u;
    float4 val  = up[(size_t)r * 1024 + c4];
    float4 gate = up[(size_t)r * 1024 + 512 + c4];
    float4 o;
    o.x = val.x * 0.5f * gate.x * (1.f + erff(gate.x * 0.70710678f));
    o.y = val.y * 0.5f * gate.y * (1.f + erff(gate.y * 0.70710678f));
    o.z = val.z * 0.5f * gate.z * (1.f + erff(gate.z * 0.70710678f));
    o.w = val.w * 0.5f * gate.w * (1.f + erff(gate.w * 0.70710678f));
    uint32_t h0, h1, l0, l1;
    split2(o.x, o.y, h0, l0);
    split2(o.z, o.w, h1, l1);
    ((uint2*)fhi)[i] = make_uint2(h0, h1);
    ((uint2*)flo)[i] = make_uint2(l0, l1);
}

// ---------------- host orchestration ----------------------------------------
extern "C" void kernel_launch(void* const* d_in, const int* in_sizes, int n_in,
                              void* d_out, int out_size)
{
    const float* x        = (const float*)d_in[0];
    const void*  edges    = d_in[1];
    const float* cond     = (const float*)d_in[2];
    const float* bn_w     = (const float*)d_in[3];
    const float* bn_b     = (const float*)d_in[4];
    const float* gcn_in_w = (const float*)d_in[5];
    const float* gcn_in_b = (const float*)d_in[6];
    const float* gcn_out_w= (const float*)d_in[7];
    const float* gcn_out_b= (const float*)d_in[8];
    const float* Wq       = (const float*)d_in[9];
    const float* Wk       = (const float*)d_in[10];
    const float* Wv       = (const float*)d_in[11];
    const float* Wo       = (const float*)d_in[12];
    const float* ln2_w    = (const float*)d_in[13];
    const float* ln2_b    = (const float*)d_in[14];
    const float* ln3_w    = (const float*)d_in[15];
    const float* ln3_b    = (const float*)d_in[16];
    const float* geglu_w  = (const float*)d_in[17];
    const float* geglu_b  = (const float*)d_in[18];
    const float* ffo_w    = (const float*)d_in[19];
    const float* ffo_b    = (const float*)d_in[20];
    float* out = (float*)d_out;

    float *h, *b1, *b2, *b3, *kb, *vb, *f, *u;
    __nv_bfloat16 *bt0, *bt1, *cs;
    cudaGetSymbolAddress((void**)&h,  g_h);
    cudaGetSymbolAddress((void**)&b1, g_b1);
    cudaGetSymbolAddress((void**)&b2, g_b2);
    cudaGetSymbolAddress((void**)&b3, g_b3);
    cudaGetSymbolAddress((void**)&kb, g_kb);
    cudaGetSymbolAddress((void**)&vb, g_vb);
    cudaGetSymbolAddress((void**)&f,  g_f);
    cudaGetSymbolAddress((void**)&u,  g_u);
    cudaGetSymbolAddress((void**)&bt0, g_bt0);
    cudaGetSymbolAddress((void**)&bt1, g_bt1);
    cudaGetSymbolAddress((void**)&cs, g_cs);

    __nv_bfloat16* b1h = (__nv_bfloat16*)b1;
    __nv_bfloat16* b1l = b1h + (size_t)NN*DD;
    __nv_bfloat16* b3h = (__nv_bfloat16*)b3;
    __nv_bfloat16* b3l = b3h + (size_t)NN*DD;
    __nv_bfloat16* fh  = (__nv_bfloat16*)f;
    __nv_bfloat16* fl  = fh + (size_t)NN*2048;
    __nv_bfloat16* csh = cs;
    __nv_bfloat16* csl = cs + (size_t)BSZ*MM*DD;

    cudaFuncSetAttribute(attn_kernel,
                         cudaFuncAttributeMaxDynamicSharedMemorySize, ATT_SMEM);
    cudaFuncSetAttribute(mm_gemm,
                         cudaFuncAttributeMaxDynamicSharedMemorySize, MM_SMEM);

    const size_t OFF_GIN = 0, OFF_GOUT = 262144, OFF_L0 = 524288, PER_L = 4194304;
    auto G = [&](const __nv_bfloat16* Ah, const __nv_bfloat16* Al, size_t off,
                 float* C, int M, int N, int K, const float* bias, const float* add) {
        mm_gemm<<<dim3(N/128, M/128), 256, MM_SMEM>>>(
            Ah, Al, bt0 + off, bt1 + off, C, M, N, K, bias, add);
    };

    // ---- ordered so launch #5 (0-based) is the first mm_gemm (ncu -s 5) ----
    zero_stats<<<NN / 256, 256>>>();                                     // 0
    bn_partial<<<dim3(2, 16), 256>>>(x);                                 // 1
    bn_apply<<<(NN * DD / 4) / 256, 256>>>(x, bn_w, bn_b, b1h, b1l);     // 2
    wsplit<<<dim3(16, 16, 1), dim3(32, 8)>>>(gcn_in_w, bt0 + OFF_GIN,
                                             bt1 + OFF_GIN, 512, 512, 0, 0); // 3
    detect_kernel<<<1, 256>>>((const int*)edges);                        // 4
    G(b1h, b1l, OFF_GIN, b2, NN, DD, DD, nullptr, nullptr);              // 5 <- profiled
    convert_kernel<<<(2*EE + 255) / 256, 256>>>(edges);                  // 6
    deg_kernel<<<EE / 256, 256>>>();                                     // 7
    dinv_kernel<<<NN / 256, 256>>>();                                    // 8
    gcn_init<<<(NN * DD) / 256, 256>>>(b2, gcn_in_b, nullptr, h);        // 9
    gcn_scatter<<<EE / 8, 256>>>(b2, h);                                 // 10

    // remaining weight splits
    wsplit<<<dim3(16, 16, 1), dim3(32, 8)>>>(gcn_out_w, bt0 + OFF_GOUT, bt1 + OFF_GOUT, 512, 512, 0, 0);
    wsplit<<<dim3(16, 16, 4), dim3(32, 8)>>>(Wq, bt0 + OFF_L0,          bt1 + OFF_L0,          512, 512, 262144, PER_L);
    wsplit<<<dim3(16, 16, 4), dim3(32, 8)>>>(Wk, bt0 + OFF_L0 + 262144, bt1 + OFF_L0 + 262144, 512, 512, 262144, PER_L);
    wsplit<<<dim3(16, 16, 4), dim3(32, 8)>>>(Wv, bt0 + OFF_L0 + 524288, bt1 + OFF_L0 + 524288, 512, 512, 262144, PER_L);
    wsplit<<<dim3(16, 16, 4), dim3(32, 8)>>>(Wo, bt0 + OFF_L0 + 786432, bt1 + OFF_L0 + 786432, 512, 512, 262144, PER_L);
    wsplit<<<dim3(128, 16, 4), dim3(32, 8)>>>(geglu_w, bt0 + OFF_L0 + 1048576, bt1 + OFF_L0 + 1048576, 512, 4096, 2097152, PER_L);
    wsplit<<<dim3(16, 64, 4), dim3(32, 8)>>>(ffo_w, bt0 + OFF_L0 + 3145728, bt1 + OFF_L0 + 3145728, 2048, 512, 1048576, PER_L);
    fsplit<<<(BSZ*MM*DD/4) / 256, 256>>>(cond, csh, csl);

    // ---- transformer layers ----
    for (int i = 0; i < LL; i++) {
        size_t base = OFF_L0 + (size_t)i * PER_L;
        ln_kernel<<<NN / 8, 256>>>(h, ln2_w + i*DD, ln2_b + i*DD, b1h, b1l);
        G(b1h, b1l, base,           b2, NN,     512, DD, nullptr, nullptr);
        G(csh, csl, base + 262144,  kb, BSZ*MM, 512, DD, nullptr, nullptr);
        G(csh, csl, base + 524288,  vb, BSZ*MM, 512, DD, nullptr, nullptr);
        attn_kernel<<<dim3(HH, BSZ, 4), 256, ATT_SMEM>>>(b2, kb, vb, b3h, b3l);
        G(b3h, b3l, base + 786432,  h,  NN,     DD,  512, nullptr, h);
        ln_kernel<<<NN / 8, 256>>>(h, ln3_w + i*DD, ln3_b + i*DD, b1h, b1l);
        G(b1h, b1l, base + 1048576, u,  NN,    4096, DD, geglu_b + (size_t)i*4096, nullptr);
        geglu_kernel<<<(NN * 2048 / 4) / 256, 256>>>(fh, fl);
        G(fh, fl,   base + 3145728, h,  NN,     DD, 2048, ffo_b + i*DD, h);
    }

    // ---- GCN out + residual ----
    fsplit<<<(NN*DD/4) / 256, 256>>>(h, b1h, b1l);
    G(b1h, b1l, OFF_GOUT, b2, NN, DD, DD, nullptr, nullptr);
    gcn_init<<<(NN * DD) / 256, 256>>>(b2, gcn_out_b, x, out);
    gcn_scatter<<<EE / 8, 256>>>(b2, out);
}